// round 1
// baseline (speedup 1.0000x reference)
#include <cuda_runtime.h>
#include <cuda_bf16.h>

// Problem constants
// B=128, N=32, Do=128, Na=16, H=4, Dk=Dv=64, Dio=144
// out: value [B,N,N,1] (131072) then w [B,H,N,N] (524288), fp32

#define LEAKY(x) ((x) > 0.0f ? (x) : 0.01f * (x))

// ---------------- scratch (no allocations allowed) ----------------
__device__ float g_base[128 * 4 * 32 * 64];   // [b,h,i,e]
__device__ float g_diff[128 * 4 * 32 * 64];   // [b,h,j,e]
__device__ float g_A  [128 * 4 * 32 * 64];    // [b,h,i,m]
__device__ float g_D  [128 * 4 * 32 * 64];    // [b,h,j,m]
__device__ float g_sbb[128 * 4 * 32];         // [b,h,i]
__device__ float g_sdd[128 * 4 * 32];         // [b,h,j]
__device__ float g_sbd[128 * 4 * 32 * 32];    // [b,h,i,j]

// ==================================================================
// Kernel 1: per-batch fused: se, q/k, scores, softmax->w, xa/xp,
//           ava/avp, base = w@ava, diff = avp-ava
// grid = 128 (b), 256 threads, dynamic smem 135168 B
// ==================================================================
__global__ void k1_front(const float* __restrict__ states,
                         const float* __restrict__ policies,
                         const float* __restrict__ actions,
                         const float* __restrict__ W_se,
                         const float* __restrict__ b_se,
                         const float* __restrict__ W_sape,
                         const float* __restrict__ b_sape,
                         const float* __restrict__ Wk,
                         const float* __restrict__ Wq,
                         const float* __restrict__ Wv,
                         float* __restrict__ out_w)
{
    extern __shared__ float sm[];
    const int tid = threadIdx.x;
    const int b = blockIdx.x;

    float* s_states = sm;             // 4096
    float* s_w      = sm + 4096;      // 4096  (scores -> softmax w)
    float* s_act    = sm + 8192;      // 512
    float* s_pol    = sm + 8704;      // 512
    // phase A (dead after softmax):
    float* s_se     = sm + 9216;      // 4096
    float* s_q      = sm + 13312;     // 4*32*65 = 8320 (padded stride 65)
    float* s_k      = sm + 21632;     // 8320  -> ends 29952
    // phase B (reuses phase-A region):
    float* s_xa     = sm + 9216;      // 4096
    float* s_xp     = sm + 13312;     // 4096
    float* s_ava    = sm + 17408;     // 8192
    float* s_avp    = sm + 25600;     // 8192  -> ends 33792

    for (int o = tid; o < 4096; o += 256) s_states[o] = states[b * 4096 + o];
    for (int o = tid; o < 512; o += 256) {
        s_act[o] = actions[b * 512 + o];
        s_pol[o] = policies[b * 512 + o];
    }
    __syncthreads();

    // se = leaky(states @ W_se + b_se)   [32,128]
    for (int o = tid; o < 4096; o += 256) {
        int n = o >> 7, c = o & 127;
        const float* srow = s_states + n * 128;
        float acc = b_se[c];
        #pragma unroll 8
        for (int d = 0; d < 128; d++) acc += srow[d] * W_se[d * 128 + c];
        s_se[o] = LEAKY(acc);
    }
    __syncthreads();

    // q,k = se @ Wq[h], se @ Wk[h]   [4][32][64]
    for (int o = tid; o < 8192; o += 256) {
        int h = o >> 11, n = (o >> 6) & 31, e = o & 63;
        const float* srow = s_se + n * 128;
        const float* wq = Wq + h * 8192 + e;
        const float* wk = Wk + h * 8192 + e;
        float aq = 0.f, ak = 0.f;
        #pragma unroll 8
        for (int d = 0; d < 128; d++) {
            float s = srow[d];
            aq += s * wq[d * 64];
            ak += s * wk[d * 64];
        }
        s_q[(h * 32 + n) * 65 + e] = aq;
        s_k[(h * 32 + n) * 65 + e] = ak;
    }
    __syncthreads();

    // scores[h,i,k2] = q.k / 8
    for (int o = tid; o < 4096; o += 256) {
        int h = o >> 10, i = (o >> 5) & 31, k2 = o & 31;
        const float* qr = s_q + (h * 32 + i) * 65;
        const float* kr = s_k + (h * 32 + k2) * 65;
        float acc = 0.f;
        #pragma unroll
        for (int e = 0; e < 64; e++) acc += qr[e] * kr[e];
        s_w[o] = acc * 0.125f;
    }
    __syncthreads();

    // softmax over k2 for each of 128 rows (h,i)
    if (tid < 128) {
        float* row = s_w + tid * 32;
        float mx = row[0];
        #pragma unroll
        for (int j = 1; j < 32; j++) mx = fmaxf(mx, row[j]);
        float s = 0.f;
        #pragma unroll
        for (int j = 0; j < 32; j++) { float ex = __expf(row[j] - mx); row[j] = ex; s += ex; }
        float inv = 1.f / s;
        #pragma unroll
        for (int j = 0; j < 32; j++) row[j] *= inv;
    }
    __syncthreads();

    // write w output
    for (int o = tid; o < 4096; o += 256) out_w[b * 4096 + o] = s_w[o];

    // xa/xp = leaky([states|actions/policies] @ W_sape + b)  [32,128]
    for (int o = tid; o < 4096; o += 256) {
        int n = o >> 7, c = o & 127;
        const float* srow = s_states + n * 128;
        float acc = b_sape[c];
        #pragma unroll 8
        for (int d = 0; d < 128; d++) acc += srow[d] * W_sape[d * 128 + c];
        float aa = 0.f, pp = 0.f;
        #pragma unroll
        for (int t = 0; t < 16; t++) {
            float wv = W_sape[(128 + t) * 128 + c];
            aa += s_act[n * 16 + t] * wv;
            pp += s_pol[n * 16 + t] * wv;
        }
        s_xa[o] = LEAKY(acc + aa);
        s_xp[o] = LEAKY(acc + pp);
    }
    __syncthreads();

    // ava/avp = xa/xp @ Wv[h]    [4][32][64]
    for (int o = tid; o < 8192; o += 256) {
        int h = o >> 11, n = (o >> 6) & 31, e = o & 63;
        const float* xar = s_xa + n * 128;
        const float* xpr = s_xp + n * 128;
        const float* wv = Wv + h * 8192 + e;
        float aa = 0.f, pp = 0.f;
        #pragma unroll 8
        for (int d = 0; d < 128; d++) {
            float w2 = wv[d * 64];
            aa += xar[d] * w2;
            pp += xpr[d] * w2;
        }
        s_ava[o] = aa;
        s_avp[o] = pp;
    }
    __syncthreads();

    // base[h,i,e] = sum_k w[h,i,k]*ava[h,k,e] ; diff = avp - ava
    for (int o = tid; o < 8192; o += 256) {
        int h = o >> 11, i = (o >> 6) & 31, e = o & 63;
        const float* wrow = s_w + h * 1024 + i * 32;
        const float* av = s_ava + h * 2048 + e;
        float acc = 0.f;
        #pragma unroll
        for (int k2 = 0; k2 < 32; k2++) acc += wrow[k2] * av[k2 * 64];
        g_base[b * 8192 + o] = acc;
        g_diff[b * 8192 + o] = s_avp[o] - s_ava[o];
    }
}

// ==================================================================
// Kernel 2: per (b,h): center base/diff, moments s_bb/s_dd/s_bd,
//           A = (cb*g)@W1h, D = (cd*g)@W1h
// grid = 512 (b*4+h), 256 threads
// ==================================================================
__global__ void k2_moments(const float* __restrict__ ln_g,
                           const float* __restrict__ W_f1)
{
    __shared__ float s_cb[32 * 65], s_cd[32 * 65];
    __shared__ float s_W1[64 * 64];
    __shared__ float s_g[64];
    const int tid = threadIdx.x;
    const int bh = blockIdx.x;
    const int h = bh & 3;

    for (int o = tid; o < 2048; o += 256) {
        int i = o >> 6, e = o & 63;
        s_cb[i * 65 + e] = g_base[bh * 2048 + o];
        s_cd[i * 65 + e] = g_diff[bh * 2048 + o];
    }
    for (int o = tid; o < 4096; o += 256)
        s_W1[o] = W_f1[(h * 64 + (o >> 6)) * 64 + (o & 63)];
    if (tid < 64) s_g[tid] = ln_g[h * 64 + tid];
    __syncthreads();

    // center rows, compute s_bb/s_dd (means over e)
    if (tid < 64) {
        int i = tid & 31;
        float* buf = (tid < 32) ? s_cb : s_cd;
        float acc = 0.f;
        #pragma unroll
        for (int e = 0; e < 64; e++) acc += buf[i * 65 + e];
        float mu = acc * (1.f / 64.f);
        float v = 0.f;
        #pragma unroll
        for (int e = 0; e < 64; e++) {
            float c = buf[i * 65 + e] - mu;
            buf[i * 65 + e] = c;
            v += c * c;
        }
        v *= (1.f / 64.f);
        if (tid < 32) g_sbb[bh * 32 + i] = v;
        else          g_sdd[bh * 32 + i] = v;
    }
    __syncthreads();

    // s_bd[i,j] = mean_e cb[i]*cd[j]
    for (int o = tid; o < 1024; o += 256) {
        int i = o >> 5, j = o & 31;
        const float* cbr = s_cb + i * 65;
        const float* cdr = s_cd + j * 65;
        float acc = 0.f;
        #pragma unroll
        for (int e = 0; e < 64; e++) acc += cbr[e] * cdr[e];
        g_sbd[bh * 1024 + o] = acc * (1.f / 64.f);
    }
    __syncthreads();

    // multiply by ln gains in place
    for (int o = tid; o < 2048; o += 256) {
        int i = o >> 6, e = o & 63;
        s_cb[i * 65 + e] *= s_g[e];
        s_cd[i * 65 + e] *= s_g[e];
    }
    __syncthreads();

    // A[i,m], D[i,m]
    for (int o = tid; o < 2048; o += 256) {
        int i = o >> 6, m = o & 63;
        const float* cbr = s_cb + i * 65;
        const float* cdr = s_cd + i * 65;
        float aA = 0.f, aD = 0.f;
        #pragma unroll
        for (int e = 0; e < 64; e++) {
            float w1 = s_W1[e * 64 + m];
            aA += cbr[e] * w1;
            aD += cdr[e] * w1;
        }
        g_A[bh * 2048 + o] = aA;
        g_D[bh * 2048 + o] = aD;
    }
}

// ==================================================================
// Kernel 3: per b: value[b,i,j] = leaky(hidden) @ W_f2 with
//   hidden[m] = C0[m] + sum_h rsq[h,j]*(A[h,i,m] + w[h,i,j]*D[h,j,m])
//   rsq = rsqrt(s_bb + 2w*s_bd + w^2*s_dd + eps)
// grid = 128 (b), 256 threads
// ==================================================================
__global__ void k3_value(const float* __restrict__ out_w,
                         const float* __restrict__ ln_b,
                         const float* __restrict__ W_f1,
                         const float* __restrict__ W_f2,
                         float* __restrict__ out_v)
{
    __shared__ float s_D[4 * 32 * 68];   // padded stride 68
    __shared__ float s_C0[64], s_W2[64];
    __shared__ float s_sdd[128];
    __shared__ float s_wi[128], s_sbd[128], s_rsq[128];
    __shared__ float s_Ai[256];
    __shared__ float s_sbb[4];
    const int tid = threadIdx.x;
    const int b = blockIdx.x;

    for (int o = tid; o < 8192; o += 256) {
        int hj = o >> 6, m = o & 63;
        s_D[hj * 68 + m] = g_D[b * 8192 + o];
    }
    if (tid < 64) {
        float acc = 0.f;
        #pragma unroll 4
        for (int f = 0; f < 256; f++) acc += ln_b[f] * W_f1[f * 64 + tid];
        s_C0[tid] = acc;
        s_W2[tid] = W_f2[tid];
    }
    if (tid < 128) s_sdd[tid] = g_sdd[b * 128 + tid];
    __syncthreads();

    for (int i = 0; i < 32; i++) {
        if (tid < 4) s_sbb[tid] = g_sbb[(b * 4 + tid) * 32 + i];
        if (tid < 128) {
            int h = tid >> 5, j = tid & 31;
            s_wi[tid]  = out_w[b * 4096 + h * 1024 + i * 32 + j];
            s_sbd[tid] = g_sbd[(b * 4 + h) * 1024 + i * 32 + j];
        }
        s_Ai[tid] = g_A[b * 8192 + (tid >> 6) * 2048 + i * 64 + (tid & 63)];
        __syncthreads();

        if (tid < 128) {
            int h = tid >> 5;
            float w = s_wi[tid];
            float var = s_sbb[h] + 2.f * w * s_sbd[tid] + w * w * s_sdd[tid];
            s_rsq[tid] = rsqrtf(var + 1e-5f);
        }
        __syncthreads();

        int j = tid >> 3, part = tid & 7;
        float acc = 0.f;
        #pragma unroll
        for (int mm = 0; mm < 8; mm++) {
            int m = part * 8 + mm;
            float hid = s_C0[m];
            #pragma unroll
            for (int h = 0; h < 4; h++) {
                float r = s_rsq[h * 32 + j];
                float w = s_wi[h * 32 + j];
                hid += r * (s_Ai[h * 64 + m] + w * s_D[(h * 32 + j) * 68 + m]);
            }
            acc += LEAKY(hid) * s_W2[m];
        }
        acc += __shfl_xor_sync(0xffffffff, acc, 4);
        acc += __shfl_xor_sync(0xffffffff, acc, 2);
        acc += __shfl_xor_sync(0xffffffff, acc, 1);
        if (part == 0) out_v[b * 1024 + i * 32 + j] = acc;
        __syncthreads();
    }
}

// ==================================================================
extern "C" void kernel_launch(void* const* d_in, const int* in_sizes, int n_in,
                              void* d_out, int out_size) {
    const float* states   = (const float*)d_in[0];
    const float* policies = (const float*)d_in[1];
    const float* actions  = (const float*)d_in[2];
    const float* W_se     = (const float*)d_in[3];
    const float* b_se     = (const float*)d_in[4];
    const float* W_sape   = (const float*)d_in[5];
    const float* b_sape   = (const float*)d_in[6];
    const float* Wk       = (const float*)d_in[7];
    const float* Wq       = (const float*)d_in[8];
    const float* Wv       = (const float*)d_in[9];
    const float* ln_g     = (const float*)d_in[10];
    const float* ln_b     = (const float*)d_in[11];
    const float* W_f1     = (const float*)d_in[12];
    const float* W_f2     = (const float*)d_in[13];

    float* out_v = (float*)d_out;                    // [B,N,N,1] = 131072
    float* out_w = (float*)d_out + 128 * 32 * 32;    // [B,H,N,N] = 524288

    const int K1_SMEM = 33792 * sizeof(float);  // 135168 B
    cudaFuncSetAttribute(k1_front, cudaFuncAttributeMaxDynamicSharedMemorySize, K1_SMEM);

    k1_front<<<128, 256, K1_SMEM>>>(states, policies, actions, W_se, b_se,
                                    W_sape, b_sape, Wk, Wq, Wv, out_w);
    k2_moments<<<512, 256>>>(ln_g, W_f1);
    k3_value<<<128, 256>>>(out_w, ln_b, W_f1, W_f2, out_v);
}

// round 2
// speedup vs baseline: 2.0703x; 2.0703x over previous
#include <cuda_runtime.h>

// B=128, N=32, Do=128, Na=16, H=4, Dk=Dv=64, Dio=144
// out: value [B,N,N,1] (131072) then w [B,H,N,N] (524288), fp32

#define LEAKY(x) ((x) > 0.0f ? (x) : 0.01f * (x))

// shared-memory layout (float offsets), phase-overlaid regions:
//  R1: q -> ava -> A ;  R2: k -> avp -> cb ;  R3: cd ;  X0: states -> D
//  X2: se -> xa ;  X3: xp
#define OFF_W    0        // 4096  softmax weights (live whole kernel)
#define OFF_SBD  4096     // 4096
#define OFF_R1   8192     // 8320
#define OFF_R2   16512    // 8320
#define OFF_R3   24832    // 8320
#define OFF_X0   33152    // 8320
#define OFF_ACT  41472    // 512
#define OFF_POL  41984    // 512
#define OFF_X2   42496    // 4096
#define OFF_X3   46592    // 4096
#define OFF_SBB  50688    // 128
#define OFF_SDD  50816    // 128
#define OFF_RSQ  50944    // 128
#define OFF_C0   51072    // 64
#define OFF_W2   51136    // 64
#define OFF_CP   51200    // 512
#define SMEM_FLOATS 51712
#define SMEM_BYTES (SMEM_FLOATS * 4)

__global__ void __launch_bounds__(512, 1)
fused_gat_kernel(const float* __restrict__ states,
                 const float* __restrict__ policies,
                 const float* __restrict__ actions,
                 const float* __restrict__ W_se,
                 const float* __restrict__ b_se,
                 const float* __restrict__ W_sape,
                 const float* __restrict__ b_sape,
                 const float* __restrict__ Wk,
                 const float* __restrict__ Wq,
                 const float* __restrict__ Wv,
                 const float* __restrict__ ln_g,
                 const float* __restrict__ ln_b,
                 const float* __restrict__ W_f1,
                 const float* __restrict__ W_f2,
                 float* __restrict__ out_v,
                 float* __restrict__ out_w)
{
    extern __shared__ float sm[];
    const int t = threadIdx.x;
    const int b = blockIdx.x;

    float* s_w      = sm + OFF_W;
    float* s_sbd    = sm + OFF_SBD;
    float* s_states = sm + OFF_X0;
    float* s_act    = sm + OFF_ACT;
    float* s_pol    = sm + OFF_POL;
    float* s_se     = sm + OFF_X2;
    float* s_xa     = sm + OFF_X2;
    float* s_xp     = sm + OFF_X3;
    float* s_q      = sm + OFF_R1;   // stride 65
    float* s_k      = sm + OFF_R2;   // stride 65
    float* s_ava    = sm + OFF_R1;   // packed [h][n][64]
    float* s_avp    = sm + OFF_R2;   // packed
    float* s_cb     = sm + OFF_R2;   // stride 65 (after avp dead)
    float* s_cd     = sm + OFF_R3;   // stride 65
    float* s_A      = sm + OFF_R1;   // packed [h*32+i][64]
    float* s_D      = sm + OFF_X0;   // stride 65
    float* s_sbb    = sm + OFF_SBB;
    float* s_sdd    = sm + OFF_SDD;
    float* s_rsq    = sm + OFF_RSQ;
    float* s_C0     = sm + OFF_C0;
    float* s_W2     = sm + OFF_W2;
    float* s_cp     = sm + OFF_CP;

    // ---------------- P0: loads + C0 partials ----------------
    #pragma unroll
    for (int o = t; o < 4096; o += 512) s_states[o] = states[b * 4096 + o];
    s_act[t] = actions[b * 512 + t];
    s_pol[t] = policies[b * 512 + t];
    {
        int m = t & 63, fg = t >> 6;
        float acc = 0.f;
        #pragma unroll 8
        for (int f = fg * 32; f < fg * 32 + 32; f++)
            acc += ln_b[f] * W_f1[f * 64 + m];
        s_cp[fg * 64 + m] = acc;
    }
    if (t < 64) s_W2[t] = W_f2[t];
    __syncthreads();
    if (t < 64) {
        float acc = 0.f;
        #pragma unroll
        for (int g2 = 0; g2 < 8; g2++) acc += s_cp[g2 * 64 + t];
        s_C0[t] = acc;
    }

    // ---------------- P1: se = leaky(states @ W_se + b) ----------------
    {
        int n = t >> 4, cg = t & 15, c = cg * 8;
        float acc[8];
        #pragma unroll
        for (int k = 0; k < 8; k++) acc[k] = b_se[c + k];
        const float* srow = s_states + n * 128;
        #pragma unroll 4
        for (int d = 0; d < 128; d++) {
            float s = srow[d];
            float4 w0 = *(const float4*)(W_se + d * 128 + c);
            float4 w1 = *(const float4*)(W_se + d * 128 + c + 4);
            acc[0] += s * w0.x; acc[1] += s * w0.y; acc[2] += s * w0.z; acc[3] += s * w0.w;
            acc[4] += s * w1.x; acc[5] += s * w1.y; acc[6] += s * w1.z; acc[7] += s * w1.w;
        }
        #pragma unroll
        for (int k = 0; k < 8; k++) s_se[n * 128 + c + k] = LEAKY(acc[k]);
    }
    __syncthreads();

    // ---------------- P2: q,k = se @ Wq/Wk ----------------
    {
        int h = t >> 7, u = t & 127;
        int eg = u & 15, e0 = eg * 4, nr = u >> 4;
        float aq[4][4], ak[4][4];
        #pragma unroll
        for (int r = 0; r < 4; r++)
            #pragma unroll
            for (int c = 0; c < 4; c++) { aq[r][c] = 0.f; ak[r][c] = 0.f; }
        const float* wqb = Wq + h * 8192 + e0;
        const float* wkb = Wk + h * 8192 + e0;
        #pragma unroll 2
        for (int d = 0; d < 128; d++) {
            float4 wq4 = *(const float4*)(wqb + d * 64);
            float4 wk4 = *(const float4*)(wkb + d * 64);
            #pragma unroll
            for (int r = 0; r < 4; r++) {
                float s = s_se[(nr + 8 * r) * 128 + d];
                aq[r][0] += s * wq4.x; aq[r][1] += s * wq4.y; aq[r][2] += s * wq4.z; aq[r][3] += s * wq4.w;
                ak[r][0] += s * wk4.x; ak[r][1] += s * wk4.y; ak[r][2] += s * wk4.z; ak[r][3] += s * wk4.w;
            }
        }
        #pragma unroll
        for (int r = 0; r < 4; r++) {
            int row = h * 32 + nr + 8 * r;
            #pragma unroll
            for (int c = 0; c < 4; c++) {
                s_q[row * 65 + e0 + c] = aq[r][c];
                s_k[row * 65 + e0 + c] = ak[r][c];
            }
        }
    }
    __syncthreads();

    // ---------------- P3: scores + softmax -> w ----------------
    {
        int h = t >> 7, rem = t & 127;
        int i = rem >> 2, k2g = rem & 3;
        float acc[8];
        #pragma unroll
        for (int kk = 0; kk < 8; kk++) acc[kk] = 0.f;
        const float* qr = s_q + (h * 32 + i) * 65;
        const float* kb = s_k + (h * 32 + k2g * 8) * 65;
        #pragma unroll 4
        for (int e = 0; e < 64; e++) {
            float qv = qr[e];
            #pragma unroll
            for (int kk = 0; kk < 8; kk++)
                acc[kk] += qv * kb[kk * 65 + e];
        }
        #pragma unroll
        for (int kk = 0; kk < 8; kk++)
            s_w[h * 1024 + i * 32 + k2g * 8 + kk] = acc[kk] * 0.125f;
    }
    __syncthreads();
    if (t < 128) {
        float* row = s_w + t * 32;
        float mx = row[0];
        #pragma unroll
        for (int j = 1; j < 32; j++) mx = fmaxf(mx, row[j]);
        float s = 0.f;
        #pragma unroll
        for (int j = 0; j < 32; j++) { float ex = __expf(row[j] - mx); row[j] = ex; s += ex; }
        float inv = 1.f / s;
        #pragma unroll
        for (int j = 0; j < 32; j++) row[j] *= inv;
    }
    __syncthreads();
    #pragma unroll
    for (int o = t; o < 4096; o += 512) out_w[b * 4096 + o] = s_w[o];

    // ---------------- P4: xa/xp ----------------
    {
        int n = t >> 4, cg = t & 15, c = cg * 8;
        float acc[8];
        #pragma unroll
        for (int k = 0; k < 8; k++) acc[k] = b_sape[c + k];
        const float* srow = s_states + n * 128;
        #pragma unroll 4
        for (int d = 0; d < 128; d++) {
            float s = srow[d];
            float4 w0 = *(const float4*)(W_sape + d * 128 + c);
            float4 w1 = *(const float4*)(W_sape + d * 128 + c + 4);
            acc[0] += s * w0.x; acc[1] += s * w0.y; acc[2] += s * w0.z; acc[3] += s * w0.w;
            acc[4] += s * w1.x; acc[5] += s * w1.y; acc[6] += s * w1.z; acc[7] += s * w1.w;
        }
        float aa[8], ap[8];
        #pragma unroll
        for (int k = 0; k < 8; k++) { aa[k] = acc[k]; ap[k] = acc[k]; }
        #pragma unroll
        for (int tt = 0; tt < 16; tt++) {
            float sa = s_act[n * 16 + tt];
            float sp = s_pol[n * 16 + tt];
            float4 w0 = *(const float4*)(W_sape + (128 + tt) * 128 + c);
            float4 w1 = *(const float4*)(W_sape + (128 + tt) * 128 + c + 4);
            aa[0] += sa * w0.x; aa[1] += sa * w0.y; aa[2] += sa * w0.z; aa[3] += sa * w0.w;
            aa[4] += sa * w1.x; aa[5] += sa * w1.y; aa[6] += sa * w1.z; aa[7] += sa * w1.w;
            ap[0] += sp * w0.x; ap[1] += sp * w0.y; ap[2] += sp * w0.z; ap[3] += sp * w0.w;
            ap[4] += sp * w1.x; ap[5] += sp * w1.y; ap[6] += sp * w1.z; ap[7] += sp * w1.w;
        }
        #pragma unroll
        for (int k = 0; k < 8; k++) {
            s_xa[n * 128 + c + k] = LEAKY(aa[k]);
            s_xp[n * 128 + c + k] = LEAKY(ap[k]);
        }
    }
    __syncthreads();

    // ---------------- P5: ava/avp = xa/xp @ Wv ----------------
    {
        int h = t >> 7, u = t & 127;
        int eg = u & 15, e0 = eg * 4, nr = u >> 4;
        float aa[4][4], ap[4][4];
        #pragma unroll
        for (int r = 0; r < 4; r++)
            #pragma unroll
            for (int c = 0; c < 4; c++) { aa[r][c] = 0.f; ap[r][c] = 0.f; }
        const float* wvb = Wv + h * 8192 + e0;
        #pragma unroll 2
        for (int d = 0; d < 128; d++) {
            float4 wv4 = *(const float4*)(wvb + d * 64);
            #pragma unroll
            for (int r = 0; r < 4; r++) {
                float sa = s_xa[(nr + 8 * r) * 128 + d];
                float sp = s_xp[(nr + 8 * r) * 128 + d];
                aa[r][0] += sa * wv4.x; aa[r][1] += sa * wv4.y; aa[r][2] += sa * wv4.z; aa[r][3] += sa * wv4.w;
                ap[r][0] += sp * wv4.x; ap[r][1] += sp * wv4.y; ap[r][2] += sp * wv4.z; ap[r][3] += sp * wv4.w;
            }
        }
        #pragma unroll
        for (int r = 0; r < 4; r++) {
            int base = h * 2048 + (nr + 8 * r) * 64 + e0;
            #pragma unroll
            for (int c = 0; c < 4; c++) {
                s_ava[base + c] = aa[r][c];
                s_avp[base + c] = ap[r][c];
            }
        }
    }
    __syncthreads();

    // ---------------- P6a: cd = avp - ava ----------------
    #pragma unroll
    for (int o = t; o < 8192; o += 512) {
        int row = o >> 6, e = o & 63;
        s_cd[row * 65 + e] = s_avp[o] - s_ava[o];
    }
    __syncthreads();

    // ---------------- P6b: cb = w @ ava  (into R2, avp dead) ----------------
    {
        int h = t >> 7, u = t & 127;
        int i = u >> 2, eg = u & 3, e0 = eg * 16;
        float acc[16];
        #pragma unroll
        for (int k = 0; k < 16; k++) acc[k] = 0.f;
        const float* wrow = s_w + h * 1024 + i * 32;
        const float* av = s_ava + h * 2048 + e0;
        #pragma unroll 4
        for (int k2 = 0; k2 < 32; k2++) {
            float wv = wrow[k2];
            const float4* a4 = (const float4*)(av + k2 * 64);
            float4 v0 = a4[0], v1 = a4[1], v2 = a4[2], v3 = a4[3];
            acc[0] += wv * v0.x; acc[1] += wv * v0.y; acc[2] += wv * v0.z; acc[3] += wv * v0.w;
            acc[4] += wv * v1.x; acc[5] += wv * v1.y; acc[6] += wv * v1.z; acc[7] += wv * v1.w;
            acc[8] += wv * v2.x; acc[9] += wv * v2.y; acc[10] += wv * v2.z; acc[11] += wv * v2.w;
            acc[12] += wv * v3.x; acc[13] += wv * v3.y; acc[14] += wv * v3.z; acc[15] += wv * v3.w;
        }
        float* cbr = s_cb + (h * 32 + i) * 65 + e0;
        #pragma unroll
        for (int k = 0; k < 16; k++) cbr[k] = acc[k];
    }
    __syncthreads();

    // ---------------- P7a: center rows, sbb/sdd ----------------
    if (t < 256) {
        float* row = ((t < 128) ? s_cb : s_cd) + (t & 127) * 65;
        float acc = 0.f;
        #pragma unroll 8
        for (int e = 0; e < 64; e++) acc += row[e];
        float mu = acc * (1.f / 64.f);
        float v = 0.f;
        #pragma unroll 8
        for (int e = 0; e < 64; e++) {
            float c = row[e] - mu;
            row[e] = c;
            v += c * c;
        }
        v *= (1.f / 64.f);
        if (t < 128) s_sbb[t] = v; else s_sdd[t & 127] = v;
    }
    __syncthreads();

    // ---------------- P7b: sbd[i,j] = mean_e cb[i]*cd[j] ----------------
    {
        int h = t >> 7, u = t & 127;
        int i = u >> 2, jg = u & 3;
        float acc[8];
        #pragma unroll
        for (int jj = 0; jj < 8; jj++) acc[jj] = 0.f;
        const float* cbr = s_cb + (h * 32 + i) * 65;
        const float* cdr = s_cd + (h * 32 + jg * 8) * 65;
        #pragma unroll 4
        for (int e = 0; e < 64; e++) {
            float bv = cbr[e];
            #pragma unroll
            for (int jj = 0; jj < 8; jj++)
                acc[jj] += bv * cdr[jj * 65 + e];
        }
        #pragma unroll
        for (int jj = 0; jj < 8; jj++)
            s_sbd[h * 1024 + i * 32 + jg * 8 + jj] = acc[jj] * (1.f / 64.f);
    }
    __syncthreads();

    // ---------------- P7c: scale centered cb/cd by ln_g ----------------
    #pragma unroll
    for (int o = t; o < 8192; o += 512) {
        int row = o >> 6, e = o & 63;
        float g = ln_g[(row >> 5) * 64 + e];
        s_cb[row * 65 + e] *= g;
        s_cd[row * 65 + e] *= g;
    }
    __syncthreads();

    // ---------------- P8: A = cb@W1h, D = cd@W1h ----------------
    {
        int h = t >> 7, u = t & 127;
        int eg = u & 15, m0 = eg * 4, nr = u >> 4;
        float aA[4][4], aD[4][4];
        #pragma unroll
        for (int r = 0; r < 4; r++)
            #pragma unroll
            for (int c = 0; c < 4; c++) { aA[r][c] = 0.f; aD[r][c] = 0.f; }
        const float* w1b = W_f1 + h * 64 * 64 + m0;
        #pragma unroll 2
        for (int e = 0; e < 64; e++) {
            float4 w4 = *(const float4*)(w1b + e * 64);
            #pragma unroll
            for (int r = 0; r < 4; r++) {
                int row = h * 32 + nr + 8 * r;
                float bv = s_cb[row * 65 + e];
                float dv = s_cd[row * 65 + e];
                aA[r][0] += bv * w4.x; aA[r][1] += bv * w4.y; aA[r][2] += bv * w4.z; aA[r][3] += bv * w4.w;
                aD[r][0] += dv * w4.x; aD[r][1] += dv * w4.y; aD[r][2] += dv * w4.z; aD[r][3] += dv * w4.w;
            }
        }
        #pragma unroll
        for (int r = 0; r < 4; r++) {
            int row = h * 32 + nr + 8 * r;
            *(float4*)(s_A + row * 64 + m0) = make_float4(aA[r][0], aA[r][1], aA[r][2], aA[r][3]);
            #pragma unroll
            for (int c = 0; c < 4; c++)
                s_D[row * 65 + m0 + c] = aD[r][c];
        }
    }
    __syncthreads();

    // ---------------- P9: value ----------------
    {
        int j = t >> 4, part = t & 15, m0 = part * 4;
        for (int i = 0; i < 32; i++) {
            if (t < 128) {
                int h = t >> 5, jj = t & 31;
                float w = s_w[h * 1024 + i * 32 + jj];
                float var = s_sbb[h * 32 + i] + 2.f * w * s_sbd[h * 1024 + i * 32 + jj]
                            + w * w * s_sdd[h * 32 + jj];
                s_rsq[t] = rsqrtf(var + 1e-5f);
            }
            __syncthreads();
            float rq[4], wv[4];
            #pragma unroll
            for (int h = 0; h < 4; h++) {
                rq[h] = s_rsq[h * 32 + j];
                wv[h] = s_w[h * 1024 + i * 32 + j];
            }
            float acc = 0.f;
            #pragma unroll
            for (int mm = 0; mm < 4; mm++) {
                int m = m0 + mm;
                float hid = s_C0[m];
                #pragma unroll
                for (int h = 0; h < 4; h++)
                    hid += rq[h] * (s_A[(h * 32 + i) * 64 + m] + wv[h] * s_D[(h * 32 + j) * 65 + m]);
                acc += LEAKY(hid) * s_W2[m];
            }
            acc += __shfl_xor_sync(0xffffffffu, acc, 8);
            acc += __shfl_xor_sync(0xffffffffu, acc, 4);
            acc += __shfl_xor_sync(0xffffffffu, acc, 2);
            acc += __shfl_xor_sync(0xffffffffu, acc, 1);
            if (part == 0) out_v[b * 1024 + i * 32 + j] = acc;
            __syncthreads();
        }
    }
}

extern "C" void kernel_launch(void* const* d_in, const int* in_sizes, int n_in,
                              void* d_out, int out_size) {
    const float* states   = (const float*)d_in[0];
    const float* policies = (const float*)d_in[1];
    const float* actions  = (const float*)d_in[2];
    const float* W_se     = (const float*)d_in[3];
    const float* b_se     = (const float*)d_in[4];
    const float* W_sape   = (const float*)d_in[5];
    const float* b_sape   = (const float*)d_in[6];
    const float* Wk       = (const float*)d_in[7];
    const float* Wq       = (const float*)d_in[8];
    const float* Wv       = (const float*)d_in[9];
    const float* ln_g     = (const float*)d_in[10];
    const float* ln_b     = (const float*)d_in[11];
    const float* W_f1     = (const float*)d_in[12];
    const float* W_f2     = (const float*)d_in[13];

    float* out_v = (float*)d_out;                    // [B,N,N,1] = 131072
    float* out_w = (float*)d_out + 128 * 32 * 32;    // [B,H,N,N] = 524288

    static int configured = 0;
    if (!configured) {
        cudaFuncSetAttribute(fused_gat_kernel,
                             cudaFuncAttributeMaxDynamicSharedMemorySize, SMEM_BYTES);
        configured = 1;
    }

    fused_gat_kernel<<<128, 512, SMEM_BYTES>>>(states, policies, actions,
                                               W_se, b_se, W_sape, b_sape,
                                               Wk, Wq, Wv, ln_g, ln_b,
                                               W_f1, W_f2, out_v, out_w);
}

// round 3
// speedup vs baseline: 2.1134x; 1.0208x over previous
#include <cuda_runtime.h>

// B=128, N=32, Do=128, Na=16, H=4, Dk=Dv=64, Dio=144
// out: value [B,N,N,1] (131072) then w [B,H,N,N] (524288), fp32

#define LEAKY(x) ((x) > 0.0f ? (x) : 0.01f * (x))

// shared layout (float offsets); overlaid regions:
//  R1: q(68) -> ava(64) -> A(64) ; R2: k(68) -> avp(64) -> cb(68)
//  R3: cd(68) ; X0: states -> D(64) ; X2: se -> xa ; X3: xp
#define OFF_W    0        // 4096
#define OFF_SBD  4096     // 4096  (sbd -> rsq in place)
#define OFF_R1   8192     // 8704
#define OFF_R2   16896    // 8704
#define OFF_R3   25600    // 8704
#define OFF_X0   34304    // 8704
#define OFF_ACT  43008    // 512
#define OFF_POL  43520    // 512
#define OFF_X2   44032    // 4096
#define OFF_X3   48128    // 4096
#define OFF_SBB  52224    // 128
#define OFF_SDD  52352    // 128
#define OFF_C0   52480    // 64
#define OFF_W2   52544    // 64
#define OFF_CP   52608    // 512
#define SMEM_FLOATS 53120
#define SMEM_BYTES (SMEM_FLOATS * 4)   // 212480

__global__ void __launch_bounds__(512, 1)
fused_gat_kernel(const float* __restrict__ states,
                 const float* __restrict__ policies,
                 const float* __restrict__ actions,
                 const float* __restrict__ W_se,
                 const float* __restrict__ b_se,
                 const float* __restrict__ W_sape,
                 const float* __restrict__ b_sape,
                 const float* __restrict__ Wk,
                 const float* __restrict__ Wq,
                 const float* __restrict__ Wv,
                 const float* __restrict__ ln_g,
                 const float* __restrict__ ln_b,
                 const float* __restrict__ W_f1,
                 const float* __restrict__ W_f2,
                 float* __restrict__ out_v,
                 float* __restrict__ out_w)
{
    extern __shared__ float sm[];
    const int t = threadIdx.x;
    const int b = blockIdx.x;

    float* s_w      = sm + OFF_W;
    float* s_sbd    = sm + OFF_SBD;   // later: rsq
    float* s_states = sm + OFF_X0;
    float* s_act    = sm + OFF_ACT;
    float* s_pol    = sm + OFF_POL;
    float* s_se     = sm + OFF_X2;
    float* s_xa     = sm + OFF_X2;
    float* s_xp     = sm + OFF_X3;
    float* s_q      = sm + OFF_R1;    // stride 68
    float* s_k      = sm + OFF_R2;    // stride 68
    float* s_ava    = sm + OFF_R1;    // packed 64
    float* s_avp    = sm + OFF_R2;    // packed 64
    float* s_cb     = sm + OFF_R2;    // stride 68
    float* s_cd     = sm + OFF_R3;    // stride 68
    float* s_A      = sm + OFF_R1;    // packed 64
    float* s_D      = sm + OFF_X0;    // packed 64
    float* s_sbb    = sm + OFF_SBB;
    float* s_sdd    = sm + OFF_SDD;
    float* s_C0     = sm + OFF_C0;
    float* s_W2     = sm + OFF_W2;
    float* s_cp     = sm + OFF_CP;

    // ---------------- P0: loads + C0 partials ----------------
    {
        const float4* st4 = (const float4*)(states + b * 4096);
        #pragma unroll
        for (int g = t; g < 1024; g += 512) ((float4*)s_states)[g] = st4[g];
        if (t < 128) {
            ((float4*)s_act)[t] = ((const float4*)(actions + b * 512))[t];
            ((float4*)s_pol)[t] = ((const float4*)(policies + b * 512))[t];
        }
        int m = t & 63, fg = t >> 6;
        float acc = 0.f;
        #pragma unroll 8
        for (int f = fg * 32; f < fg * 32 + 32; f++)
            acc += ln_b[f] * W_f1[f * 64 + m];
        s_cp[fg * 64 + m] = acc;
        if (t < 64) s_W2[t] = W_f2[t];
    }
    __syncthreads();
    if (t < 64) {
        float acc = 0.f;
        #pragma unroll
        for (int g2 = 0; g2 < 8; g2++) acc += s_cp[g2 * 64 + t];
        s_C0[t] = acc;
    }

    // ---------------- P1: se = leaky(states @ W_se + b) ----------------
    {
        int n = t >> 4, c = (t & 15) * 8;
        float4 bb0 = *(const float4*)(b_se + c);
        float4 bb1 = *(const float4*)(b_se + c + 4);
        float acc[8] = {bb0.x, bb0.y, bb0.z, bb0.w, bb1.x, bb1.y, bb1.z, bb1.w};
        const float* srow = s_states + n * 128;
        #pragma unroll 1
        for (int d0 = 0; d0 < 128; d0 += 4) {
            float4 s4 = *(const float4*)(srow + d0);
            float sv[4] = {s4.x, s4.y, s4.z, s4.w};
            #pragma unroll
            for (int dd = 0; dd < 4; dd++) {
                const float* wr = W_se + (d0 + dd) * 128 + c;
                float4 w0 = *(const float4*)(wr);
                float4 w1 = *(const float4*)(wr + 4);
                float s = sv[dd];
                acc[0] += s * w0.x; acc[1] += s * w0.y; acc[2] += s * w0.z; acc[3] += s * w0.w;
                acc[4] += s * w1.x; acc[5] += s * w1.y; acc[6] += s * w1.z; acc[7] += s * w1.w;
            }
        }
        #pragma unroll
        for (int k = 0; k < 8; k++) s_se[n * 128 + c + k] = LEAKY(acc[k]);
    }
    __syncthreads();

    // ---------------- P2: q,k = se @ Wq/Wk ----------------
    {
        int h = t >> 7, u = t & 127;
        int e0 = (u & 15) * 4, nr = u >> 4;
        float aq[4][4], ak[4][4];
        #pragma unroll
        for (int r = 0; r < 4; r++)
            #pragma unroll
            for (int c = 0; c < 4; c++) { aq[r][c] = 0.f; ak[r][c] = 0.f; }
        const float* wqb = Wq + h * 8192 + e0;
        const float* wkb = Wk + h * 8192 + e0;
        #pragma unroll 1
        for (int d0 = 0; d0 < 128; d0 += 4) {
            float sv[4][4];
            #pragma unroll
            for (int r = 0; r < 4; r++) {
                float4 s4 = *(const float4*)(s_se + (nr + 8 * r) * 128 + d0);
                sv[r][0] = s4.x; sv[r][1] = s4.y; sv[r][2] = s4.z; sv[r][3] = s4.w;
            }
            #pragma unroll
            for (int dd = 0; dd < 4; dd++) {
                float4 wq4 = *(const float4*)(wqb + (d0 + dd) * 64);
                float4 wk4 = *(const float4*)(wkb + (d0 + dd) * 64);
                #pragma unroll
                for (int r = 0; r < 4; r++) {
                    float s = sv[r][dd];
                    aq[r][0] += s * wq4.x; aq[r][1] += s * wq4.y; aq[r][2] += s * wq4.z; aq[r][3] += s * wq4.w;
                    ak[r][0] += s * wk4.x; ak[r][1] += s * wk4.y; ak[r][2] += s * wk4.z; ak[r][3] += s * wk4.w;
                }
            }
        }
        #pragma unroll
        for (int r = 0; r < 4; r++) {
            int row = h * 32 + nr + 8 * r;
            *(float4*)(s_q + row * 68 + e0) = make_float4(aq[r][0], aq[r][1], aq[r][2], aq[r][3]);
            *(float4*)(s_k + row * 68 + e0) = make_float4(ak[r][0], ak[r][1], ak[r][2], ak[r][3]);
        }
    }
    __syncthreads();

    // ---------------- P3: scores ----------------
    {
        int h = t >> 7, rem = t & 127;
        int i = rem >> 2, k2g = rem & 3;
        float acc[8] = {0.f, 0.f, 0.f, 0.f, 0.f, 0.f, 0.f, 0.f};
        const float* qr = s_q + (h * 32 + i) * 68;
        const float* kb = s_k + (h * 32 + k2g * 8) * 68;
        #pragma unroll 1
        for (int e0 = 0; e0 < 64; e0 += 4) {
            float4 q4 = *(const float4*)(qr + e0);
            #pragma unroll
            for (int kk = 0; kk < 8; kk++) {
                float4 k4 = *(const float4*)(kb + kk * 68 + e0);
                acc[kk] += q4.x * k4.x + q4.y * k4.y + q4.z * k4.z + q4.w * k4.w;
            }
        }
        #pragma unroll
        for (int kk = 0; kk < 8; kk++)
            s_w[h * 1024 + i * 32 + k2g * 8 + kk] = acc[kk] * 0.125f;
    }
    __syncthreads();

    // ---------------- softmax ----------------
    if (t < 128) {
        float* row = s_w + t * 32;
        float mx = row[0];
        #pragma unroll
        for (int j = 1; j < 32; j++) mx = fmaxf(mx, row[j]);
        float s = 0.f;
        #pragma unroll
        for (int j = 0; j < 32; j++) { float ex = __expf(row[j] - mx); row[j] = ex; s += ex; }
        float inv = 1.f / s;
        #pragma unroll
        for (int j = 0; j < 32; j++) row[j] *= inv;
    }
    __syncthreads();
    #pragma unroll
    for (int g = t; g < 1024; g += 512)
        *(float4*)(out_w + b * 4096 + g * 4) = *(const float4*)(s_w + g * 4);

    // ---------------- P4: xa/xp ----------------
    {
        int n = t >> 4, c = (t & 15) * 8;
        float4 bb0 = *(const float4*)(b_sape + c);
        float4 bb1 = *(const float4*)(b_sape + c + 4);
        float base0[8] = {bb0.x, bb0.y, bb0.z, bb0.w, bb1.x, bb1.y, bb1.z, bb1.w};
        const float* srow = s_states + n * 128;
        #pragma unroll 1
        for (int d0 = 0; d0 < 128; d0 += 4) {
            float4 s4 = *(const float4*)(srow + d0);
            float sv[4] = {s4.x, s4.y, s4.z, s4.w};
            #pragma unroll
            for (int dd = 0; dd < 4; dd++) {
                const float* wr = W_sape + (d0 + dd) * 128 + c;
                float4 w0 = *(const float4*)(wr);
                float4 w1 = *(const float4*)(wr + 4);
                float s = sv[dd];
                base0[0] += s * w0.x; base0[1] += s * w0.y; base0[2] += s * w0.z; base0[3] += s * w0.w;
                base0[4] += s * w1.x; base0[5] += s * w1.y; base0[6] += s * w1.z; base0[7] += s * w1.w;
            }
        }
        float aa[8], ap[8];
        #pragma unroll
        for (int k = 0; k < 8; k++) { aa[k] = base0[k]; ap[k] = base0[k]; }
        #pragma unroll
        for (int t4 = 0; t4 < 4; t4++) {
            float4 sa4 = *(const float4*)(s_act + n * 16 + t4 * 4);
            float4 sp4 = *(const float4*)(s_pol + n * 16 + t4 * 4);
            float sav[4] = {sa4.x, sa4.y, sa4.z, sa4.w};
            float spv[4] = {sp4.x, sp4.y, sp4.z, sp4.w};
            #pragma unroll
            for (int dd = 0; dd < 4; dd++) {
                const float* wr = W_sape + (128 + t4 * 4 + dd) * 128 + c;
                float4 w0 = *(const float4*)(wr);
                float4 w1 = *(const float4*)(wr + 4);
                float sa = sav[dd], sp = spv[dd];
                aa[0] += sa * w0.x; aa[1] += sa * w0.y; aa[2] += sa * w0.z; aa[3] += sa * w0.w;
                aa[4] += sa * w1.x; aa[5] += sa * w1.y; aa[6] += sa * w1.z; aa[7] += sa * w1.w;
                ap[0] += sp * w0.x; ap[1] += sp * w0.y; ap[2] += sp * w0.z; ap[3] += sp * w0.w;
                ap[4] += sp * w1.x; ap[5] += sp * w1.y; ap[6] += sp * w1.z; ap[7] += sp * w1.w;
            }
        }
        #pragma unroll
        for (int k = 0; k < 8; k++) {
            s_xa[n * 128 + c + k] = LEAKY(aa[k]);
            s_xp[n * 128 + c + k] = LEAKY(ap[k]);
        }
    }
    __syncthreads();

    // ---------------- P5: ava/avp = xa/xp @ Wv ----------------
    {
        int h = t >> 7, u = t & 127;
        int e0 = (u & 15) * 4, nr = u >> 4;
        float aa[4][4], ap[4][4];
        #pragma unroll
        for (int r = 0; r < 4; r++)
            #pragma unroll
            for (int c = 0; c < 4; c++) { aa[r][c] = 0.f; ap[r][c] = 0.f; }
        const float* wvb = Wv + h * 8192 + e0;
        #pragma unroll 1
        for (int d0 = 0; d0 < 128; d0 += 4) {
            float av[4][4], pv[4][4];
            #pragma unroll
            for (int r = 0; r < 4; r++) {
                float4 a4 = *(const float4*)(s_xa + (nr + 8 * r) * 128 + d0);
                float4 p4 = *(const float4*)(s_xp + (nr + 8 * r) * 128 + d0);
                av[r][0] = a4.x; av[r][1] = a4.y; av[r][2] = a4.z; av[r][3] = a4.w;
                pv[r][0] = p4.x; pv[r][1] = p4.y; pv[r][2] = p4.z; pv[r][3] = p4.w;
            }
            #pragma unroll
            for (int dd = 0; dd < 4; dd++) {
                float4 w4 = *(const float4*)(wvb + (d0 + dd) * 64);
                #pragma unroll
                for (int r = 0; r < 4; r++) {
                    float sa = av[r][dd], sp = pv[r][dd];
                    aa[r][0] += sa * w4.x; aa[r][1] += sa * w4.y; aa[r][2] += sa * w4.z; aa[r][3] += sa * w4.w;
                    ap[r][0] += sp * w4.x; ap[r][1] += sp * w4.y; ap[r][2] += sp * w4.z; ap[r][3] += sp * w4.w;
                }
            }
        }
        #pragma unroll
        for (int r = 0; r < 4; r++) {
            int base = h * 2048 + (nr + 8 * r) * 64 + e0;
            *(float4*)(s_ava + base) = make_float4(aa[r][0], aa[r][1], aa[r][2], aa[r][3]);
            *(float4*)(s_avp + base) = make_float4(ap[r][0], ap[r][1], ap[r][2], ap[r][3]);
        }
    }
    __syncthreads();

    // ---------------- P6a: cd = avp - ava (stride 68) ----------------
    #pragma unroll
    for (int g = t; g < 2048; g += 512) {
        int row = g >> 4, e0 = (g & 15) * 4;
        float4 a4 = *(const float4*)(s_ava + row * 64 + e0);
        float4 p4 = *(const float4*)(s_avp + row * 64 + e0);
        *(float4*)(s_cd + row * 68 + e0) =
            make_float4(p4.x - a4.x, p4.y - a4.y, p4.z - a4.z, p4.w - a4.w);
    }
    __syncthreads();

    // ---------------- P6b: cb = w @ ava ----------------
    {
        int h = t >> 7, u = t & 127;
        int i = u >> 2, e0 = (u & 3) * 16;
        float acc[16];
        #pragma unroll
        for (int k = 0; k < 16; k++) acc[k] = 0.f;
        const float* wrow = s_w + h * 1024 + i * 32;
        const float* av = s_ava + h * 2048 + e0;
        #pragma unroll 4
        for (int k2 = 0; k2 < 32; k2++) {
            float wv = wrow[k2];
            const float4* a4 = (const float4*)(av + k2 * 64);
            float4 v0 = a4[0], v1 = a4[1], v2 = a4[2], v3 = a4[3];
            acc[0]  += wv * v0.x; acc[1]  += wv * v0.y; acc[2]  += wv * v0.z; acc[3]  += wv * v0.w;
            acc[4]  += wv * v1.x; acc[5]  += wv * v1.y; acc[6]  += wv * v1.z; acc[7]  += wv * v1.w;
            acc[8]  += wv * v2.x; acc[9]  += wv * v2.y; acc[10] += wv * v2.z; acc[11] += wv * v2.w;
            acc[12] += wv * v3.x; acc[13] += wv * v3.y; acc[14] += wv * v3.z; acc[15] += wv * v3.w;
        }
        float* cbr = s_cb + (h * 32 + i) * 68 + e0;
        #pragma unroll
        for (int q4 = 0; q4 < 4; q4++)
            *(float4*)(cbr + q4 * 4) = make_float4(acc[q4 * 4], acc[q4 * 4 + 1], acc[q4 * 4 + 2], acc[q4 * 4 + 3]);
    }
    __syncthreads();

    // ---------------- P7a: center rows, sbb/sdd ----------------
    if (t < 256) {
        float* row = ((t < 128) ? s_cb : s_cd) + (t & 127) * 68;
        float acc = 0.f;
        #pragma unroll
        for (int e0 = 0; e0 < 64; e0 += 4) {
            float4 v = *(const float4*)(row + e0);
            acc += v.x + v.y + v.z + v.w;
        }
        float mu = acc * (1.f / 64.f);
        float var = 0.f;
        #pragma unroll
        for (int e0 = 0; e0 < 64; e0 += 4) {
            float4 v = *(const float4*)(row + e0);
            v.x -= mu; v.y -= mu; v.z -= mu; v.w -= mu;
            var += v.x * v.x + v.y * v.y + v.z * v.z + v.w * v.w;
            *(float4*)(row + e0) = v;
        }
        var *= (1.f / 64.f);
        if (t < 128) s_sbb[t] = var; else s_sdd[t & 127] = var;
    }
    __syncthreads();

    // ---------------- P7b: sbd[i,j] ----------------
    {
        int h = t >> 7, u = t & 127;
        int i = u >> 2, jg = u & 3;
        float acc[8] = {0.f, 0.f, 0.f, 0.f, 0.f, 0.f, 0.f, 0.f};
        const float* cbr = s_cb + (h * 32 + i) * 68;
        const float* cdr = s_cd + (h * 32 + jg * 8) * 68;
        #pragma unroll 1
        for (int e0 = 0; e0 < 64; e0 += 4) {
            float4 b4 = *(const float4*)(cbr + e0);
            #pragma unroll
            for (int jj = 0; jj < 8; jj++) {
                float4 d4 = *(const float4*)(cdr + jj * 68 + e0);
                acc[jj] += b4.x * d4.x + b4.y * d4.y + b4.z * d4.z + b4.w * d4.w;
            }
        }
        #pragma unroll
        for (int jj = 0; jj < 8; jj++)
            s_sbd[h * 1024 + i * 32 + jg * 8 + jj] = acc[jj] * (1.f / 64.f);
    }
    __syncthreads();

    // ---------------- P7c: scale centered cb/cd by ln_g ----------------
    #pragma unroll
    for (int g = t; g < 2048; g += 512) {
        int row = g >> 4, e0 = (g & 15) * 4;
        float4 g4 = *(const float4*)(ln_g + (row >> 5) * 64 + e0);
        float4 b4 = *(const float4*)(s_cb + row * 68 + e0);
        float4 d4 = *(const float4*)(s_cd + row * 68 + e0);
        b4.x *= g4.x; b4.y *= g4.y; b4.z *= g4.z; b4.w *= g4.w;
        d4.x *= g4.x; d4.y *= g4.y; d4.z *= g4.z; d4.w *= g4.w;
        *(float4*)(s_cb + row * 68 + e0) = b4;
        *(float4*)(s_cd + row * 68 + e0) = d4;
    }
    __syncthreads();

    // ---------------- P8: A = cb@W1h, D = cd@W1h (packed 64) ----------------
    {
        int h = t >> 7, u = t & 127;
        int m0 = (u & 15) * 4, nr = u >> 4;
        float aA[4][4], aD[4][4];
        #pragma unroll
        for (int r = 0; r < 4; r++)
            #pragma unroll
            for (int c = 0; c < 4; c++) { aA[r][c] = 0.f; aD[r][c] = 0.f; }
        const float* w1b = W_f1 + h * 4096 + m0;
        #pragma unroll 1
        for (int e0 = 0; e0 < 64; e0 += 4) {
            float bvv[4][4], dvv[4][4];
            #pragma unroll
            for (int r = 0; r < 4; r++) {
                int row = h * 32 + nr + 8 * r;
                float4 b4 = *(const float4*)(s_cb + row * 68 + e0);
                float4 d4 = *(const float4*)(s_cd + row * 68 + e0);
                bvv[r][0] = b4.x; bvv[r][1] = b4.y; bvv[r][2] = b4.z; bvv[r][3] = b4.w;
                dvv[r][0] = d4.x; dvv[r][1] = d4.y; dvv[r][2] = d4.z; dvv[r][3] = d4.w;
            }
            #pragma unroll
            for (int ee = 0; ee < 4; ee++) {
                float4 w4 = *(const float4*)(w1b + (e0 + ee) * 64);
                #pragma unroll
                for (int r = 0; r < 4; r++) {
                    float bv = bvv[r][ee], dv = dvv[r][ee];
                    aA[r][0] += bv * w4.x; aA[r][1] += bv * w4.y; aA[r][2] += bv * w4.z; aA[r][3] += bv * w4.w;
                    aD[r][0] += dv * w4.x; aD[r][1] += dv * w4.y; aD[r][2] += dv * w4.z; aD[r][3] += dv * w4.w;
                }
            }
        }
        #pragma unroll
        for (int r = 0; r < 4; r++) {
            int row = h * 32 + nr + 8 * r;
            *(float4*)(s_A + row * 64 + m0) = make_float4(aA[r][0], aA[r][1], aA[r][2], aA[r][3]);
            *(float4*)(s_D + row * 64 + m0) = make_float4(aD[r][0], aD[r][1], aD[r][2], aD[r][3]);
        }
    }
    __syncthreads();

    // ---------------- P8b: rsq in place of sbd ----------------
    #pragma unroll
    for (int g = t; g < 1024; g += 512) {
        int h = g >> 8, i = (g >> 3) & 31, j0 = (g & 7) * 4;
        int base = h * 1024 + i * 32 + j0;
        float4 w4 = *(const float4*)(s_w + base);
        float4 s4 = *(const float4*)(s_sbd + base);
        float4 dd4 = *(const float4*)(s_sdd + h * 32 + j0);
        float bb = s_sbb[h * 32 + i];
        float4 r;
        r.x = rsqrtf(bb + 2.f * w4.x * s4.x + w4.x * w4.x * dd4.x + 1e-5f);
        r.y = rsqrtf(bb + 2.f * w4.y * s4.y + w4.y * w4.y * dd4.y + 1e-5f);
        r.z = rsqrtf(bb + 2.f * w4.z * s4.z + w4.z * w4.z * dd4.z + 1e-5f);
        r.w = rsqrtf(bb + 2.f * w4.w * s4.w + w4.w * w4.w * dd4.w + 1e-5f);
        *(float4*)(s_sbd + base) = r;
    }
    __syncthreads();

    // ---------------- P9: value (sync-free loop) ----------------
    {
        int j = t >> 4, part = t & 15, m0 = part * 4;
        float4 C04 = *(const float4*)(s_C0 + m0);
        float4 W24 = *(const float4*)(s_W2 + m0);
        float4 D4[4];
        #pragma unroll
        for (int h = 0; h < 4; h++)
            D4[h] = *(const float4*)(s_D + (h * 32 + j) * 64 + m0);
        #pragma unroll 1
        for (int i = 0; i < 32; i++) {
            float4 hid = C04;
            #pragma unroll
            for (int h = 0; h < 4; h++) {
                int idx = h * 1024 + i * 32 + j;
                float rq = s_sbd[idx];
                float wv = s_w[idx];
                float4 A4 = *(const float4*)(s_A + (h * 32 + i) * 64 + m0);
                hid.x += rq * (A4.x + wv * D4[h].x);
                hid.y += rq * (A4.y + wv * D4[h].y);
                hid.z += rq * (A4.z + wv * D4[h].z);
                hid.w += rq * (A4.w + wv * D4[h].w);
            }
            float acc = LEAKY(hid.x) * W24.x + LEAKY(hid.y) * W24.y
                      + LEAKY(hid.z) * W24.z + LEAKY(hid.w) * W24.w;
            acc += __shfl_xor_sync(0xffffffffu, acc, 8);
            acc += __shfl_xor_sync(0xffffffffu, acc, 4);
            acc += __shfl_xor_sync(0xffffffffu, acc, 2);
            acc += __shfl_xor_sync(0xffffffffu, acc, 1);
            if (part == 0) out_v[b * 1024 + i * 32 + j] = acc;
        }
    }
}

extern "C" void kernel_launch(void* const* d_in, const int* in_sizes, int n_in,
                              void* d_out, int out_size) {
    const float* states   = (const float*)d_in[0];
    const float* policies = (const float*)d_in[1];
    const float* actions  = (const float*)d_in[2];
    const float* W_se     = (const float*)d_in[3];
    const float* b_se     = (const float*)d_in[4];
    const float* W_sape   = (const float*)d_in[5];
    const float* b_sape   = (const float*)d_in[6];
    const float* Wk       = (const float*)d_in[7];
    const float* Wq       = (const float*)d_in[8];
    const float* Wv       = (const float*)d_in[9];
    const float* ln_g     = (const float*)d_in[10];
    const float* ln_b     = (const float*)d_in[11];
    const float* W_f1     = (const float*)d_in[12];
    const float* W_f2     = (const float*)d_in[13];

    float* out_v = (float*)d_out;                    // [B,N,N,1]
    float* out_w = (float*)d_out + 128 * 32 * 32;    // [B,H,N,N]

    static int configured = 0;
    if (!configured) {
        cudaFuncSetAttribute(fused_gat_kernel,
                             cudaFuncAttributeMaxDynamicSharedMemorySize, SMEM_BYTES);
        configured = 1;
    }

    fused_gat_kernel<<<128, 512, SMEM_BYTES>>>(states, policies, actions,
                                               W_se, b_se, W_sape, b_sape,
                                               Wk, Wq, Wv, ln_g, ln_b,
                                               W_f1, W_f2, out_v, out_w);
}

// round 4
// speedup vs baseline: 2.2785x; 1.0781x over previous
#include <cuda_runtime.h>

// B=128, N=32, Do=128, Na=16, H=4, Dk=Dv=64, Dio=144
// out: value [B,N,N,1] (131072) then w [B,H,N,N] (524288), fp32

#define LEAKY(x) ((x) > 0.0f ? (x) : 0.01f * (x))

typedef unsigned long long u64t;

__device__ __forceinline__ u64t bcast2(float x) {
    u64t r; asm("mov.b64 %0, {%1, %1};" : "=l"(r) : "f"(x)); return r;
}
__device__ __forceinline__ u64t fma2(u64t a, u64t b, u64t c) {
    u64t d; asm("fma.rn.f32x2 %0, %1, %2, %3;" : "=l"(d) : "l"(a), "l"(b), "l"(c)); return d;
}
__device__ __forceinline__ float2 unpk(u64t v) {
    float2 f; asm("mov.b64 {%0, %1}, %2;" : "=f"(f.x), "=f"(f.y) : "l"(v)); return f;
}

// shared layout (float offsets); overlaid regions:
#define OFF_W    0        // 4096
#define OFF_SBD  4096     // 4096  (sbd -> rsq in place)
#define OFF_R1   8192     // 8704
#define OFF_R2   16896    // 8704
#define OFF_R3   25600    // 8704
#define OFF_X0   34304    // 8704
#define OFF_ACT  43008    // 512
#define OFF_POL  43520    // 512
#define OFF_X2   44032    // 4096
#define OFF_X3   48128    // 4096
#define OFF_SBB  52224    // 128
#define OFF_SDD  52352    // 128
#define OFF_C0   52480    // 64
#define OFF_W2   52544    // 64
#define OFF_CP   52608    // 512
#define SMEM_FLOATS 53120
#define SMEM_BYTES (SMEM_FLOATS * 4)   // 212480

__global__ void __launch_bounds__(512, 1)
fused_gat_kernel(const float* __restrict__ states,
                 const float* __restrict__ policies,
                 const float* __restrict__ actions,
                 const float* __restrict__ W_se,
                 const float* __restrict__ b_se,
                 const float* __restrict__ W_sape,
                 const float* __restrict__ b_sape,
                 const float* __restrict__ Wk,
                 const float* __restrict__ Wq,
                 const float* __restrict__ Wv,
                 const float* __restrict__ ln_g,
                 const float* __restrict__ ln_b,
                 const float* __restrict__ W_f1,
                 const float* __restrict__ W_f2,
                 float* __restrict__ out_v,
                 float* __restrict__ out_w)
{
    extern __shared__ float sm[];
    const int t = threadIdx.x;
    const int b = blockIdx.x;

    float* s_w      = sm + OFF_W;
    float* s_sbd    = sm + OFF_SBD;   // later: rsq
    float* s_states = sm + OFF_X0;
    float* s_act    = sm + OFF_ACT;
    float* s_pol    = sm + OFF_POL;
    float* s_se     = sm + OFF_X2;
    float* s_xa     = sm + OFF_X2;
    float* s_xp     = sm + OFF_X3;
    float* s_q      = sm + OFF_R1;    // stride 68
    float* s_k      = sm + OFF_R2;    // stride 68
    float* s_ava    = sm + OFF_R1;    // packed 64
    float* s_avp    = sm + OFF_R2;    // packed 64
    float* s_cb     = sm + OFF_R2;    // stride 68
    float* s_cd     = sm + OFF_R3;    // stride 68
    float* s_A      = sm + OFF_R1;    // packed 64
    float* s_D      = sm + OFF_X0;    // packed 64
    float* s_sbb    = sm + OFF_SBB;
    float* s_sdd    = sm + OFF_SDD;
    float* s_C0     = sm + OFF_C0;
    float* s_W2     = sm + OFF_W2;
    float* s_cp     = sm + OFF_CP;

    // ---------------- P0: loads + C0 partials ----------------
    {
        const float4* st4 = (const float4*)(states + b * 4096);
        #pragma unroll
        for (int g = t; g < 1024; g += 512) ((float4*)s_states)[g] = st4[g];
        if (t < 128) {
            ((float4*)s_act)[t] = ((const float4*)(actions + b * 512))[t];
            ((float4*)s_pol)[t] = ((const float4*)(policies + b * 512))[t];
        }
        int m = t & 63, fg = t >> 6;
        float acc = 0.f;
        #pragma unroll 8
        for (int f = fg * 32; f < fg * 32 + 32; f++)
            acc += ln_b[f] * W_f1[f * 64 + m];
        s_cp[fg * 64 + m] = acc;
        if (t < 64) s_W2[t] = W_f2[t];
    }
    __syncthreads();
    if (t < 64) {
        float acc = 0.f;
        #pragma unroll
        for (int g2 = 0; g2 < 8; g2++) acc += s_cp[g2 * 64 + t];
        s_C0[t] = acc;
    }

    // ---------------- P1: se = leaky(states @ W_se + b) ----------------
    {
        int n = t >> 4, c = (t & 15) * 8;
        ulonglong2 bb0 = *(const ulonglong2*)(b_se + c);
        ulonglong2 bb1 = *(const ulonglong2*)(b_se + c + 4);
        u64t acc[4] = {bb0.x, bb0.y, bb1.x, bb1.y};
        const float* srow = s_states + n * 128;
        #pragma unroll 2
        for (int d0 = 0; d0 < 128; d0 += 4) {
            float4 s4 = *(const float4*)(srow + d0);
            float sv[4] = {s4.x, s4.y, s4.z, s4.w};
            #pragma unroll
            for (int dd = 0; dd < 4; dd++) {
                const float* wr = W_se + (d0 + dd) * 128 + c;
                ulonglong2 w0 = *(const ulonglong2*)(wr);
                ulonglong2 w1 = *(const ulonglong2*)(wr + 4);
                u64t s2 = bcast2(sv[dd]);
                acc[0] = fma2(s2, w0.x, acc[0]);
                acc[1] = fma2(s2, w0.y, acc[1]);
                acc[2] = fma2(s2, w1.x, acc[2]);
                acc[3] = fma2(s2, w1.y, acc[3]);
            }
        }
        #pragma unroll
        for (int k = 0; k < 4; k++) {
            float2 f = unpk(acc[k]);
            s_se[n * 128 + c + 2 * k]     = LEAKY(f.x);
            s_se[n * 128 + c + 2 * k + 1] = LEAKY(f.y);
        }
    }
    __syncthreads();

    // ---------------- P2: q,k = se @ Wq/Wk ----------------
    {
        int h = t >> 7, u = t & 127;
        int e0 = (u & 15) * 4, nr = u >> 4;
        u64t aq[4][2], ak[4][2];
        #pragma unroll
        for (int r = 0; r < 4; r++) { aq[r][0] = 0; aq[r][1] = 0; ak[r][0] = 0; ak[r][1] = 0; }
        const float* wqb = Wq + h * 8192 + e0;
        const float* wkb = Wk + h * 8192 + e0;
        #pragma unroll 2
        for (int d0 = 0; d0 < 128; d0 += 4) {
            float sv[4][4];
            #pragma unroll
            for (int r = 0; r < 4; r++) {
                float4 s4 = *(const float4*)(s_se + (nr + 8 * r) * 128 + d0);
                sv[r][0] = s4.x; sv[r][1] = s4.y; sv[r][2] = s4.z; sv[r][3] = s4.w;
            }
            #pragma unroll
            for (int dd = 0; dd < 4; dd++) {
                ulonglong2 wq2 = *(const ulonglong2*)(wqb + (d0 + dd) * 64);
                ulonglong2 wk2 = *(const ulonglong2*)(wkb + (d0 + dd) * 64);
                #pragma unroll
                for (int r = 0; r < 4; r++) {
                    u64t s2 = bcast2(sv[r][dd]);
                    aq[r][0] = fma2(s2, wq2.x, aq[r][0]);
                    aq[r][1] = fma2(s2, wq2.y, aq[r][1]);
                    ak[r][0] = fma2(s2, wk2.x, ak[r][0]);
                    ak[r][1] = fma2(s2, wk2.y, ak[r][1]);
                }
            }
        }
        #pragma unroll
        for (int r = 0; r < 4; r++) {
            int row = h * 32 + nr + 8 * r;
            float2 q0 = unpk(aq[r][0]), q1 = unpk(aq[r][1]);
            float2 k0 = unpk(ak[r][0]), k1 = unpk(ak[r][1]);
            *(float4*)(s_q + row * 68 + e0) = make_float4(q0.x, q0.y, q1.x, q1.y);
            *(float4*)(s_k + row * 68 + e0) = make_float4(k0.x, k0.y, k1.x, k1.y);
        }
    }
    __syncthreads();

    // ---------------- P3: scores ----------------
    {
        int h = t >> 7, rem = t & 127;
        int i = rem >> 2, k2g = rem & 3;
        u64t acc2[8] = {0, 0, 0, 0, 0, 0, 0, 0};
        const float* qr = s_q + (h * 32 + i) * 68;
        const float* kb = s_k + (h * 32 + k2g * 8) * 68;
        #pragma unroll 2
        for (int e0 = 0; e0 < 64; e0 += 4) {
            ulonglong2 q2 = *(const ulonglong2*)(qr + e0);
            #pragma unroll
            for (int kk = 0; kk < 8; kk++) {
                ulonglong2 k2v = *(const ulonglong2*)(kb + kk * 68 + e0);
                acc2[kk] = fma2(q2.x, k2v.x, acc2[kk]);
                acc2[kk] = fma2(q2.y, k2v.y, acc2[kk]);
            }
        }
        #pragma unroll
        for (int kk = 0; kk < 8; kk++) {
            float2 f = unpk(acc2[kk]);
            s_w[h * 1024 + i * 32 + k2g * 8 + kk] = (f.x + f.y) * 0.125f;
        }
    }
    __syncthreads();

    // ---------------- softmax ----------------
    if (t < 128) {
        float* row = s_w + t * 32;
        float mx = row[0];
        #pragma unroll
        for (int j = 1; j < 32; j++) mx = fmaxf(mx, row[j]);
        float s = 0.f;
        #pragma unroll
        for (int j = 0; j < 32; j++) { float ex = __expf(row[j] - mx); row[j] = ex; s += ex; }
        float inv = 1.f / s;
        #pragma unroll
        for (int j = 0; j < 32; j++) row[j] *= inv;
    }
    __syncthreads();
    #pragma unroll
    for (int g = t; g < 1024; g += 512)
        *(float4*)(out_w + b * 4096 + g * 4) = *(const float4*)(s_w + g * 4);

    // ---------------- P4: xa/xp ----------------
    {
        int n = t >> 4, c = (t & 15) * 8;
        ulonglong2 bb0 = *(const ulonglong2*)(b_sape + c);
        ulonglong2 bb1 = *(const ulonglong2*)(b_sape + c + 4);
        u64t bs[4] = {bb0.x, bb0.y, bb1.x, bb1.y};
        const float* srow = s_states + n * 128;
        #pragma unroll 2
        for (int d0 = 0; d0 < 128; d0 += 4) {
            float4 s4 = *(const float4*)(srow + d0);
            float sv[4] = {s4.x, s4.y, s4.z, s4.w};
            #pragma unroll
            for (int dd = 0; dd < 4; dd++) {
                const float* wr = W_sape + (d0 + dd) * 128 + c;
                ulonglong2 w0 = *(const ulonglong2*)(wr);
                ulonglong2 w1 = *(const ulonglong2*)(wr + 4);
                u64t s2 = bcast2(sv[dd]);
                bs[0] = fma2(s2, w0.x, bs[0]);
                bs[1] = fma2(s2, w0.y, bs[1]);
                bs[2] = fma2(s2, w1.x, bs[2]);
                bs[3] = fma2(s2, w1.y, bs[3]);
            }
        }
        u64t aa[4], ap[4];
        #pragma unroll
        for (int k = 0; k < 4; k++) { aa[k] = bs[k]; ap[k] = bs[k]; }
        #pragma unroll
        for (int t4 = 0; t4 < 4; t4++) {
            float4 sa4 = *(const float4*)(s_act + n * 16 + t4 * 4);
            float4 sp4 = *(const float4*)(s_pol + n * 16 + t4 * 4);
            float sav[4] = {sa4.x, sa4.y, sa4.z, sa4.w};
            float spv[4] = {sp4.x, sp4.y, sp4.z, sp4.w};
            #pragma unroll
            for (int dd = 0; dd < 4; dd++) {
                const float* wr = W_sape + (128 + t4 * 4 + dd) * 128 + c;
                ulonglong2 w0 = *(const ulonglong2*)(wr);
                ulonglong2 w1 = *(const ulonglong2*)(wr + 4);
                u64t sa2 = bcast2(sav[dd]);
                u64t sp2 = bcast2(spv[dd]);
                aa[0] = fma2(sa2, w0.x, aa[0]);
                aa[1] = fma2(sa2, w0.y, aa[1]);
                aa[2] = fma2(sa2, w1.x, aa[2]);
                aa[3] = fma2(sa2, w1.y, aa[3]);
                ap[0] = fma2(sp2, w0.x, ap[0]);
                ap[1] = fma2(sp2, w0.y, ap[1]);
                ap[2] = fma2(sp2, w1.x, ap[2]);
                ap[3] = fma2(sp2, w1.y, ap[3]);
            }
        }
        #pragma unroll
        for (int k = 0; k < 4; k++) {
            float2 fa = unpk(aa[k]), fp = unpk(ap[k]);
            s_xa[n * 128 + c + 2 * k]     = LEAKY(fa.x);
            s_xa[n * 128 + c + 2 * k + 1] = LEAKY(fa.y);
            s_xp[n * 128 + c + 2 * k]     = LEAKY(fp.x);
            s_xp[n * 128 + c + 2 * k + 1] = LEAKY(fp.y);
        }
    }
    __syncthreads();

    // ---------------- P5: ava/avp = xa/xp @ Wv ----------------
    {
        int h = t >> 7, u = t & 127;
        int e0 = (u & 15) * 4, nr = u >> 4;
        u64t aa[4][2], ap[4][2];
        #pragma unroll
        for (int r = 0; r < 4; r++) { aa[r][0] = 0; aa[r][1] = 0; ap[r][0] = 0; ap[r][1] = 0; }
        const float* wvb = Wv + h * 8192 + e0;
        #pragma unroll 2
        for (int d0 = 0; d0 < 128; d0 += 4) {
            float av[4][4], pv[4][4];
            #pragma unroll
            for (int r = 0; r < 4; r++) {
                float4 a4 = *(const float4*)(s_xa + (nr + 8 * r) * 128 + d0);
                float4 p4 = *(const float4*)(s_xp + (nr + 8 * r) * 128 + d0);
                av[r][0] = a4.x; av[r][1] = a4.y; av[r][2] = a4.z; av[r][3] = a4.w;
                pv[r][0] = p4.x; pv[r][1] = p4.y; pv[r][2] = p4.z; pv[r][3] = p4.w;
            }
            #pragma unroll
            for (int dd = 0; dd < 4; dd++) {
                ulonglong2 w2 = *(const ulonglong2*)(wvb + (d0 + dd) * 64);
                #pragma unroll
                for (int r = 0; r < 4; r++) {
                    u64t sa2 = bcast2(av[r][dd]);
                    u64t sp2 = bcast2(pv[r][dd]);
                    aa[r][0] = fma2(sa2, w2.x, aa[r][0]);
                    aa[r][1] = fma2(sa2, w2.y, aa[r][1]);
                    ap[r][0] = fma2(sp2, w2.x, ap[r][0]);
                    ap[r][1] = fma2(sp2, w2.y, ap[r][1]);
                }
            }
        }
        #pragma unroll
        for (int r = 0; r < 4; r++) {
            int base = h * 2048 + (nr + 8 * r) * 64 + e0;
            float2 a0 = unpk(aa[r][0]), a1 = unpk(aa[r][1]);
            float2 p0 = unpk(ap[r][0]), p1 = unpk(ap[r][1]);
            *(float4*)(s_ava + base) = make_float4(a0.x, a0.y, a1.x, a1.y);
            *(float4*)(s_avp + base) = make_float4(p0.x, p0.y, p1.x, p1.y);
        }
    }
    __syncthreads();

    // ---------------- P6a: cd = avp - ava (stride 68) ----------------
    #pragma unroll
    for (int g = t; g < 2048; g += 512) {
        int row = g >> 4, e0 = (g & 15) * 4;
        float4 a4 = *(const float4*)(s_ava + row * 64 + e0);
        float4 p4 = *(const float4*)(s_avp + row * 64 + e0);
        *(float4*)(s_cd + row * 68 + e0) =
            make_float4(p4.x - a4.x, p4.y - a4.y, p4.z - a4.z, p4.w - a4.w);
    }
    __syncthreads();

    // ---------------- P6b: cb = w @ ava ----------------
    {
        int h = t >> 7, u = t & 127;
        int i = u >> 2, e0 = (u & 3) * 16;
        u64t acc[8] = {0, 0, 0, 0, 0, 0, 0, 0};
        const float* wrow = s_w + h * 1024 + i * 32;
        const float* av = s_ava + h * 2048 + e0;
        #pragma unroll 4
        for (int k2 = 0; k2 < 32; k2++) {
            u64t w2 = bcast2(wrow[k2]);
            const ulonglong2* a2 = (const ulonglong2*)(av + k2 * 64);
            ulonglong2 v0 = a2[0], v1 = a2[1], v2 = a2[2], v3 = a2[3];
            acc[0] = fma2(w2, v0.x, acc[0]);
            acc[1] = fma2(w2, v0.y, acc[1]);
            acc[2] = fma2(w2, v1.x, acc[2]);
            acc[3] = fma2(w2, v1.y, acc[3]);
            acc[4] = fma2(w2, v2.x, acc[4]);
            acc[5] = fma2(w2, v2.y, acc[5]);
            acc[6] = fma2(w2, v3.x, acc[6]);
            acc[7] = fma2(w2, v3.y, acc[7]);
        }
        float* cbr = s_cb + (h * 32 + i) * 68 + e0;
        #pragma unroll
        for (int q4 = 0; q4 < 4; q4++) {
            float2 f0 = unpk(acc[q4 * 2]);
            float2 f1 = unpk(acc[q4 * 2 + 1]);
            *(float4*)(cbr + q4 * 4) = make_float4(f0.x, f0.y, f1.x, f1.y);
        }
    }
    __syncthreads();

    // ---------------- P7a: center rows, sbb/sdd ----------------
    if (t < 256) {
        float* row = ((t < 128) ? s_cb : s_cd) + (t & 127) * 68;
        float acc = 0.f;
        #pragma unroll
        for (int e0 = 0; e0 < 64; e0 += 4) {
            float4 v = *(const float4*)(row + e0);
            acc += v.x + v.y + v.z + v.w;
        }
        float mu = acc * (1.f / 64.f);
        float var = 0.f;
        #pragma unroll
        for (int e0 = 0; e0 < 64; e0 += 4) {
            float4 v = *(const float4*)(row + e0);
            v.x -= mu; v.y -= mu; v.z -= mu; v.w -= mu;
            var += v.x * v.x + v.y * v.y + v.z * v.z + v.w * v.w;
            *(float4*)(row + e0) = v;
        }
        var *= (1.f / 64.f);
        if (t < 128) s_sbb[t] = var; else s_sdd[t & 127] = var;
    }
    __syncthreads();

    // ---------------- P7b: sbd[i,j] ----------------
    {
        int h = t >> 7, u = t & 127;
        int i = u >> 2, jg = u & 3;
        u64t acc2[8] = {0, 0, 0, 0, 0, 0, 0, 0};
        const float* cbr = s_cb + (h * 32 + i) * 68;
        const float* cdr = s_cd + (h * 32 + jg * 8) * 68;
        #pragma unroll 2
        for (int e0 = 0; e0 < 64; e0 += 4) {
            ulonglong2 b2 = *(const ulonglong2*)(cbr + e0);
            #pragma unroll
            for (int jj = 0; jj < 8; jj++) {
                ulonglong2 d2 = *(const ulonglong2*)(cdr + jj * 68 + e0);
                acc2[jj] = fma2(b2.x, d2.x, acc2[jj]);
                acc2[jj] = fma2(b2.y, d2.y, acc2[jj]);
            }
        }
        #pragma unroll
        for (int jj = 0; jj < 8; jj++) {
            float2 f = unpk(acc2[jj]);
            s_sbd[h * 1024 + i * 32 + jg * 8 + jj] = (f.x + f.y) * (1.f / 64.f);
        }
    }
    __syncthreads();

    // ---------------- P7c: scale centered cb/cd by ln_g ----------------
    #pragma unroll
    for (int g = t; g < 2048; g += 512) {
        int row = g >> 4, e0 = (g & 15) * 4;
        float4 g4 = *(const float4*)(ln_g + (row >> 5) * 64 + e0);
        float4 b4 = *(const float4*)(s_cb + row * 68 + e0);
        float4 d4 = *(const float4*)(s_cd + row * 68 + e0);
        b4.x *= g4.x; b4.y *= g4.y; b4.z *= g4.z; b4.w *= g4.w;
        d4.x *= g4.x; d4.y *= g4.y; d4.z *= g4.z; d4.w *= g4.w;
        *(float4*)(s_cb + row * 68 + e0) = b4;
        *(float4*)(s_cd + row * 68 + e0) = d4;
    }
    __syncthreads();

    // ---------------- P8: A = cb@W1h, D = cd@W1h (packed 64) ----------------
    {
        int h = t >> 7, u = t & 127;
        int m0 = (u & 15) * 4, nr = u >> 4;
        u64t aA[4][2], aD[4][2];
        #pragma unroll
        for (int r = 0; r < 4; r++) { aA[r][0] = 0; aA[r][1] = 0; aD[r][0] = 0; aD[r][1] = 0; }
        const float* w1b = W_f1 + h * 4096 + m0;
        #pragma unroll 2
        for (int e0 = 0; e0 < 64; e0 += 4) {
            float bvv[4][4], dvv[4][4];
            #pragma unroll
            for (int r = 0; r < 4; r++) {
                int row = h * 32 + nr + 8 * r;
                float4 b4 = *(const float4*)(s_cb + row * 68 + e0);
                float4 d4 = *(const float4*)(s_cd + row * 68 + e0);
                bvv[r][0] = b4.x; bvv[r][1] = b4.y; bvv[r][2] = b4.z; bvv[r][3] = b4.w;
                dvv[r][0] = d4.x; dvv[r][1] = d4.y; dvv[r][2] = d4.z; dvv[r][3] = d4.w;
            }
            #pragma unroll
            for (int ee = 0; ee < 4; ee++) {
                ulonglong2 w2 = *(const ulonglong2*)(w1b + (e0 + ee) * 64);
                #pragma unroll
                for (int r = 0; r < 4; r++) {
                    u64t bv2 = bcast2(bvv[r][ee]);
                    u64t dv2 = bcast2(dvv[r][ee]);
                    aA[r][0] = fma2(bv2, w2.x, aA[r][0]);
                    aA[r][1] = fma2(bv2, w2.y, aA[r][1]);
                    aD[r][0] = fma2(dv2, w2.x, aD[r][0]);
                    aD[r][1] = fma2(dv2, w2.y, aD[r][1]);
                }
            }
        }
        #pragma unroll
        for (int r = 0; r < 4; r++) {
            int row = h * 32 + nr + 8 * r;
            float2 A0 = unpk(aA[r][0]), A1 = unpk(aA[r][1]);
            float2 D0 = unpk(aD[r][0]), D1 = unpk(aD[r][1]);
            *(float4*)(s_A + row * 64 + m0) = make_float4(A0.x, A0.y, A1.x, A1.y);
            *(float4*)(s_D + row * 64 + m0) = make_float4(D0.x, D0.y, D1.x, D1.y);
        }
    }
    __syncthreads();

    // ---------------- P8b: rsq in place of sbd ----------------
    #pragma unroll
    for (int g = t; g < 1024; g += 512) {
        int h = g >> 8, i = (g >> 3) & 31, j0 = (g & 7) * 4;
        int base = h * 1024 + i * 32 + j0;
        float4 w4 = *(const float4*)(s_w + base);
        float4 s4 = *(const float4*)(s_sbd + base);
        float4 dd4 = *(const float4*)(s_sdd + h * 32 + j0);
        float bb = s_sbb[h * 32 + i];
        float4 r;
        r.x = rsqrtf(bb + 2.f * w4.x * s4.x + w4.x * w4.x * dd4.x + 1e-5f);
        r.y = rsqrtf(bb + 2.f * w4.y * s4.y + w4.y * w4.y * dd4.y + 1e-5f);
        r.z = rsqrtf(bb + 2.f * w4.z * s4.z + w4.z * w4.z * dd4.z + 1e-5f);
        r.w = rsqrtf(bb + 2.f * w4.w * s4.w + w4.w * w4.w * dd4.w + 1e-5f);
        *(float4*)(s_sbd + base) = r;
    }
    __syncthreads();

    // ---------------- P9: value (sync-free loop) ----------------
    {
        int j = t >> 4, part = t & 15, m0 = part * 4;
        ulonglong2 C02 = *(const ulonglong2*)(s_C0 + m0);
        float4 W24 = *(const float4*)(s_W2 + m0);
        u64t D2[4][2];
        #pragma unroll
        for (int h = 0; h < 4; h++) {
            ulonglong2 d2 = *(const ulonglong2*)(s_D + (h * 32 + j) * 64 + m0);
            D2[h][0] = d2.x; D2[h][1] = d2.y;
        }
        #pragma unroll 1
        for (int i = 0; i < 32; i++) {
            u64t hid0 = C02.x, hid1 = C02.y;
            #pragma unroll
            for (int h = 0; h < 4; h++) {
                int idx = h * 1024 + i * 32 + j;
                u64t rq2 = bcast2(s_sbd[idx]);
                u64t wv2 = bcast2(s_w[idx]);
                ulonglong2 A2 = *(const ulonglong2*)(s_A + (h * 32 + i) * 64 + m0);
                u64t t0 = fma2(wv2, D2[h][0], A2.x);
                hid0 = fma2(rq2, t0, hid0);
                u64t t1 = fma2(wv2, D2[h][1], A2.y);
                hid1 = fma2(rq2, t1, hid1);
            }
            float2 h0 = unpk(hid0), h1 = unpk(hid1);
            float acc = LEAKY(h0.x) * W24.x + LEAKY(h0.y) * W24.y
                      + LEAKY(h1.x) * W24.z + LEAKY(h1.y) * W24.w;
            acc += __shfl_xor_sync(0xffffffffu, acc, 8);
            acc += __shfl_xor_sync(0xffffffffu, acc, 4);
            acc += __shfl_xor_sync(0xffffffffu, acc, 2);
            acc += __shfl_xor_sync(0xffffffffu, acc, 1);
            if (part == 0) out_v[b * 1024 + i * 32 + j] = acc;
        }
    }
}

extern "C" void kernel_launch(void* const* d_in, const int* in_sizes, int n_in,
                              void* d_out, int out_size) {
    const float* states   = (const float*)d_in[0];
    const float* policies = (const float*)d_in[1];
    const float* actions  = (const float*)d_in[2];
    const float* W_se     = (const float*)d_in[3];
    const float* b_se     = (const float*)d_in[4];
    const float* W_sape   = (const float*)d_in[5];
    const float* b_sape   = (const float*)d_in[6];
    const float* Wk       = (const float*)d_in[7];
    const float* Wq       = (const float*)d_in[8];
    const float* Wv       = (const float*)d_in[9];
    const float* ln_g     = (const float*)d_in[10];
    const float* ln_b     = (const float*)d_in[11];
    const float* W_f1     = (const float*)d_in[12];
    const float* W_f2     = (const float*)d_in[13];

    float* out_v = (float*)d_out;                    // [B,N,N,1]
    float* out_w = (float*)d_out + 128 * 32 * 32;    // [B,H,N,N]

    static int configured = 0;
    if (!configured) {
        cudaFuncSetAttribute(fused_gat_kernel,
                             cudaFuncAttributeMaxDynamicSharedMemorySize, SMEM_BYTES);
        configured = 1;
    }

    fused_gat_kernel<<<128, 512, SMEM_BYTES>>>(states, policies, actions,
                                               W_se, b_se, W_sape, b_sape,
                                               Wk, Wq, Wv, ln_g, ln_b,
                                               W_f1, W_f2, out_v, out_w);
}

// round 9
// speedup vs baseline: 2.3548x; 1.0335x over previous
#include <cuda_runtime.h>

// B=128, N=32, Do=128, Na=16, H=4, Dk=Dv=64, Dio=144
// out: value [B,N,N,1] (131072) then w [B,H,N,N] (524288), fp32

#define LEAKY(x) ((x) > 0.0f ? (x) : 0.01f * (x))

typedef unsigned long long u64t;

__device__ __forceinline__ u64t bcast2(float x) {
    u64t r; asm("mov.b64 %0, {%1, %1};" : "=l"(r) : "f"(x)); return r;
}
__device__ __forceinline__ u64t fma2(u64t a, u64t b, u64t c) {
    u64t d; asm("fma.rn.f32x2 %0, %1, %2, %3;" : "=l"(d) : "l"(a), "l"(b), "l"(c)); return d;
}
__device__ __forceinline__ float2 unpk(u64t v) {
    float2 f; asm("mov.b64 {%0, %1}, %2;" : "=f"(f.x), "=f"(f.y) : "l"(v)); return f;
}

// ---- shared layout (float offsets) ----
#define OFF_W     0        // 4096   softmax w [h*1024+i*32+j]
#define OFF_SBD   4096     // 4096   sbd -> rsq
#define OFF_WBUF  8192     // 4096   weight staging (16KB)
#define OFF_STT   12288    // 4224   states^T [d][33]
#define OFF_ACTT  16512    // 528    actions^T [16][33]
#define OFF_POLT  17040    // 528
#define OFF_SET   17568    // 4224   se^T [c][33]  (later xa^T)
#define OFF_XPT   21792    // 4224   xp^T [c][33]
#define OFF_M1    26016    // 8704   q(68) -> ava(68) -> A(68)
#define OFF_M2    34720    // 8704   k(68) -> avp(68) -> cb(68)
#define OFF_M3    43424    // 8704   cd(68)
#define OFF_SBB   52128    // 128
#define OFF_SDD   52256    // 128
#define OFF_C0    52384    // 64
#define OFF_W2    52448    // 64
#define OFF_CP    52512    // 512
#define OFF_D     8192     // 8704   D(68) overlays WBUF+STT+ACTT head (all dead by P8)
#define SMEM_FLOATS 53024
#define SMEM_BYTES (SMEM_FLOATS * 4)   // 212096  (<= R4's proven 212480)

__global__ void __launch_bounds__(512, 1)
fused_gat_kernel(const float* __restrict__ states,
                 const float* __restrict__ policies,
                 const float* __restrict__ actions,
                 const float* __restrict__ W_se,
                 const float* __restrict__ b_se,
                 const float* __restrict__ W_sape,
                 const float* __restrict__ b_sape,
                 const float* __restrict__ Wk,
                 const float* __restrict__ Wq,
                 const float* __restrict__ Wv,
                 const float* __restrict__ ln_g,
                 const float* __restrict__ ln_b,
                 const float* __restrict__ W_f1,
                 const float* __restrict__ W_f2,
                 float* __restrict__ out_v,
                 float* __restrict__ out_w)
{
    extern __shared__ float sm[];
    const int t = threadIdx.x;
    const int b = blockIdx.x;
    const int lane = t & 31;
    const int wid = t >> 5;

    float* s_w    = sm + OFF_W;
    float* s_sbd  = sm + OFF_SBD;
    float* s_wbuf = sm + OFF_WBUF;
    float* s_stT  = sm + OFF_STT;
    float* s_actT = sm + OFF_ACTT;
    float* s_polT = sm + OFF_POLT;
    float* s_seT  = sm + OFF_SET;   // later xaT
    float* s_xpT  = sm + OFF_XPT;
    float* s_q    = sm + OFF_M1;    // stride 68
    float* s_k    = sm + OFF_M2;    // stride 68
    float* s_ava  = sm + OFF_M1;    // stride 68
    float* s_avp  = sm + OFF_M2;    // stride 68
    float* s_cb   = sm + OFF_M2;    // stride 68
    float* s_cd   = sm + OFF_M3;    // stride 68
    float* s_A    = sm + OFF_M1;    // stride 68
    float* s_D    = sm + OFF_D;     // stride 68
    float* s_sbb  = sm + OFF_SBB;
    float* s_sdd  = sm + OFF_SDD;
    float* s_C0   = sm + OFF_C0;
    float* s_W2   = sm + OFF_W2;
    float* s_cp   = sm + OFF_CP;

    // ---------------- P0: transposed loads + C0 partials ----------------
    {
        #pragma unroll
        for (int o = t; o < 4096; o += 512) {
            int n = o >> 7, d = o & 127;
            s_stT[d * 33 + n] = states[b * 4096 + o];
        }
        {
            int n = t >> 4, tt = t & 15;
            s_actT[tt * 33 + n] = actions[b * 512 + t];
            s_polT[tt * 33 + n] = policies[b * 512 + t];
        }
        int m = t & 63, fg = t >> 6;
        float acc = 0.f;
        #pragma unroll 8
        for (int f = fg * 32; f < fg * 32 + 32; f++)
            acc += ln_b[f] * W_f1[f * 64 + m];
        s_cp[fg * 64 + m] = acc;
        if (t < 64) s_W2[t] = W_f2[t];
    }
    __syncthreads();
    if (t < 64) {
        float acc = 0.f;
        #pragma unroll
        for (int g2 = 0; g2 < 8; g2++) acc += s_cp[g2 * 64 + t];
        s_C0[t] = acc;
    }

    // ---------------- P1: se^T = leaky(states @ W_se + b)^T ----------------
    // warp = c-group (8 cols), lane = n; weights broadcast from staged smem
    {
        int c0 = wid * 8;
        ulonglong2 bb0 = *(const ulonglong2*)(b_se + c0);
        ulonglong2 bb1 = *(const ulonglong2*)(b_se + c0 + 4);
        u64t acc[4] = {bb0.x, bb0.y, bb1.x, bb1.y};
        #pragma unroll 1
        for (int chunk = 0; chunk < 4; chunk++) {
            int d0 = chunk * 32;
            const float4* src = (const float4*)(W_se + d0 * 128);
            #pragma unroll
            for (int k = 0; k < 2; k++)
                ((float4*)s_wbuf)[t + k * 512] = src[t + k * 512];
            __syncthreads();
            #pragma unroll 4
            for (int d = 0; d < 32; d++) {
                u64t a2 = bcast2(s_stT[(d0 + d) * 33 + lane]);
                const ulonglong2* wr = (const ulonglong2*)(s_wbuf + d * 128 + c0);
                ulonglong2 w0 = wr[0], w1 = wr[1];
                acc[0] = fma2(a2, w0.x, acc[0]);
                acc[1] = fma2(a2, w0.y, acc[1]);
                acc[2] = fma2(a2, w1.x, acc[2]);
                acc[3] = fma2(a2, w1.y, acc[3]);
            }
            __syncthreads();
        }
        #pragma unroll
        for (int k = 0; k < 4; k++) {
            float2 f = unpk(acc[k]);
            s_seT[(c0 + 2 * k) * 33 + lane]     = LEAKY(f.x);
            s_seT[(c0 + 2 * k + 1) * 33 + lane] = LEAKY(f.y);
        }
    }

    // ---------------- P2: q = se @ Wq, then k = se @ Wk (broadcast weights) ----
    // warp = (h, e-group of 16), lane = n
    {
        int h = wid >> 2, e0 = (wid & 3) * 16;
        // ---- q ----
        u64t aq[8];
        #pragma unroll
        for (int k = 0; k < 8; k++) aq[k] = 0;
        #pragma unroll 1
        for (int chunk = 0; chunk < 8; chunk++) {
            int d0 = chunk * 16;
            #pragma unroll
            for (int k = 0; k < 2; k++) {
                int g4 = t + k * 512;
                int hh = g4 >> 8, rem = g4 & 255;
                int dd = rem >> 4, e4 = rem & 15;
                ((float4*)s_wbuf)[g4] = ((const float4*)Wq)[hh * 2048 + (d0 + dd) * 16 + e4];
            }
            __syncthreads();
            #pragma unroll 4
            for (int dd = 0; dd < 16; dd++) {
                u64t a2 = bcast2(s_seT[(d0 + dd) * 33 + lane]);
                const ulonglong2* wqr = (const ulonglong2*)(s_wbuf + h * 1024 + dd * 64 + e0);
                #pragma unroll
                for (int j = 0; j < 4; j++) {
                    ulonglong2 wq2 = wqr[j];
                    aq[2 * j]     = fma2(a2, wq2.x, aq[2 * j]);
                    aq[2 * j + 1] = fma2(a2, wq2.y, aq[2 * j + 1]);
                }
            }
            __syncthreads();
        }
        {
            int row = h * 32 + lane;
            #pragma unroll
            for (int j = 0; j < 4; j++) {
                float2 q0 = unpk(aq[2 * j]), q1 = unpk(aq[2 * j + 1]);
                *(float4*)(s_q + row * 68 + e0 + j * 4) = make_float4(q0.x, q0.y, q1.x, q1.y);
            }
        }
        // ---- k ----
        u64t ak[8];
        #pragma unroll
        for (int k = 0; k < 8; k++) ak[k] = 0;
        #pragma unroll 1
        for (int chunk = 0; chunk < 8; chunk++) {
            int d0 = chunk * 16;
            #pragma unroll
            for (int k = 0; k < 2; k++) {
                int g4 = t + k * 512;
                int hh = g4 >> 8, rem = g4 & 255;
                int dd = rem >> 4, e4 = rem & 15;
                ((float4*)s_wbuf)[g4] = ((const float4*)Wk)[hh * 2048 + (d0 + dd) * 16 + e4];
            }
            __syncthreads();
            #pragma unroll 4
            for (int dd = 0; dd < 16; dd++) {
                u64t a2 = bcast2(s_seT[(d0 + dd) * 33 + lane]);
                const ulonglong2* wkr = (const ulonglong2*)(s_wbuf + h * 1024 + dd * 64 + e0);
                #pragma unroll
                for (int j = 0; j < 4; j++) {
                    ulonglong2 wk2 = wkr[j];
                    ak[2 * j]     = fma2(a2, wk2.x, ak[2 * j]);
                    ak[2 * j + 1] = fma2(a2, wk2.y, ak[2 * j + 1]);
                }
            }
            __syncthreads();
        }
        {
            int row = h * 32 + lane;
            #pragma unroll
            for (int j = 0; j < 4; j++) {
                float2 k0 = unpk(ak[2 * j]), k1 = unpk(ak[2 * j + 1]);
                *(float4*)(s_k + row * 68 + e0 + j * 4) = make_float4(k0.x, k0.y, k1.x, k1.y);
            }
        }
    }
    __syncthreads();

    // ---------------- P3: scores ----------------
    {
        int h = t >> 7, rem = t & 127;
        int i = rem >> 2, k2g = rem & 3;
        u64t acc2[8] = {0, 0, 0, 0, 0, 0, 0, 0};
        const float* qr = s_q + (h * 32 + i) * 68;
        const float* kb = s_k + (h * 32 + k2g * 8) * 68;
        #pragma unroll 2
        for (int e0 = 0; e0 < 64; e0 += 4) {
            ulonglong2 q2 = *(const ulonglong2*)(qr + e0);
            #pragma unroll
            for (int kk = 0; kk < 8; kk++) {
                ulonglong2 k2v = *(const ulonglong2*)(kb + kk * 68 + e0);
                acc2[kk] = fma2(q2.x, k2v.x, acc2[kk]);
                acc2[kk] = fma2(q2.y, k2v.y, acc2[kk]);
            }
        }
        #pragma unroll
        for (int kk = 0; kk < 8; kk++) {
            float2 f = unpk(acc2[kk]);
            s_w[h * 1024 + i * 32 + k2g * 8 + kk] = (f.x + f.y) * 0.125f;
        }
    }
    __syncthreads();

    // ---------------- softmax ----------------
    if (t < 128) {
        float* row = s_w + t * 32;
        float mx = row[0];
        #pragma unroll
        for (int j = 1; j < 32; j++) mx = fmaxf(mx, row[j]);
        float s = 0.f;
        #pragma unroll
        for (int j = 0; j < 32; j++) { float ex = __expf(row[j] - mx); row[j] = ex; s += ex; }
        float inv = 1.f / s;
        #pragma unroll
        for (int j = 0; j < 32; j++) row[j] *= inv;
    }
    __syncthreads();
    #pragma unroll
    for (int g = t; g < 1024; g += 512)
        *(float4*)(out_w + b * 4096 + g * 4) = *(const float4*)(s_w + g * 4);

    // ---------------- P4: xa^T/xp^T (broadcast weights) ----------------
    {
        int c0 = wid * 8;
        ulonglong2 bb0 = *(const ulonglong2*)(b_sape + c0);
        ulonglong2 bb1 = *(const ulonglong2*)(b_sape + c0 + 4);
        u64t bs[4] = {bb0.x, bb0.y, bb1.x, bb1.y};
        #pragma unroll 1
        for (int chunk = 0; chunk < 4; chunk++) {
            int d0 = chunk * 32;
            const float4* src = (const float4*)(W_sape + d0 * 128);
            #pragma unroll
            for (int k = 0; k < 2; k++)
                ((float4*)s_wbuf)[t + k * 512] = src[t + k * 512];
            __syncthreads();
            #pragma unroll 4
            for (int d = 0; d < 32; d++) {
                u64t a2 = bcast2(s_stT[(d0 + d) * 33 + lane]);
                const ulonglong2* wr = (const ulonglong2*)(s_wbuf + d * 128 + c0);
                ulonglong2 w0 = wr[0], w1 = wr[1];
                bs[0] = fma2(a2, w0.x, bs[0]);
                bs[1] = fma2(a2, w0.y, bs[1]);
                bs[2] = fma2(a2, w1.x, bs[2]);
                bs[3] = fma2(a2, w1.y, bs[3]);
            }
            __syncthreads();
        }
        // action/policy tail rows 128..143 (16 rows x 128 = 2048 floats)
        u64t aa[4], ap[4];
        #pragma unroll
        for (int k = 0; k < 4; k++) { aa[k] = bs[k]; ap[k] = bs[k]; }
        ((float4*)s_wbuf)[t] = ((const float4*)(W_sape + 16384))[t];
        __syncthreads();
        #pragma unroll 4
        for (int tt = 0; tt < 16; tt++) {
            u64t av = bcast2(s_actT[tt * 33 + lane]);
            u64t pv = bcast2(s_polT[tt * 33 + lane]);
            const ulonglong2* wr = (const ulonglong2*)(s_wbuf + tt * 128 + c0);
            ulonglong2 w0 = wr[0], w1 = wr[1];
            aa[0] = fma2(av, w0.x, aa[0]);
            aa[1] = fma2(av, w0.y, aa[1]);
            aa[2] = fma2(av, w1.x, aa[2]);
            aa[3] = fma2(av, w1.y, aa[3]);
            ap[0] = fma2(pv, w0.x, ap[0]);
            ap[1] = fma2(pv, w0.y, ap[1]);
            ap[2] = fma2(pv, w1.x, ap[2]);
            ap[3] = fma2(pv, w1.y, ap[3]);
        }
        __syncthreads();   // protect WBUF before P5 refill
        #pragma unroll
        for (int k = 0; k < 4; k++) {
            float2 fa = unpk(aa[k]), fp = unpk(ap[k]);
            s_seT[(c0 + 2 * k) * 33 + lane]     = LEAKY(fa.x);   // xaT
            s_seT[(c0 + 2 * k + 1) * 33 + lane] = LEAKY(fa.y);
            s_xpT[(c0 + 2 * k) * 33 + lane]     = LEAKY(fp.x);
            s_xpT[(c0 + 2 * k + 1) * 33 + lane] = LEAKY(fp.y);
        }
    }

    // ---------------- P5: ava/avp = xa/xp @ Wv (broadcast weights) ----------------
    {
        int h = wid >> 2, e0 = (wid & 3) * 16;
        u64t aa[8], ap[8];
        #pragma unroll
        for (int k = 0; k < 8; k++) { aa[k] = 0; ap[k] = 0; }
        #pragma unroll 1
        for (int chunk = 0; chunk < 8; chunk++) {
            int d0 = chunk * 16;
            #pragma unroll
            for (int k = 0; k < 2; k++) {
                int g4 = t + k * 512;
                int hh = g4 >> 8, rem = g4 & 255;
                int dd = rem >> 4, e4 = rem & 15;
                ((float4*)s_wbuf)[g4] = ((const float4*)Wv)[hh * 2048 + (d0 + dd) * 16 + e4];
            }
            __syncthreads();
            #pragma unroll 4
            for (int dd = 0; dd < 16; dd++) {
                u64t av2 = bcast2(s_seT[(d0 + dd) * 33 + lane]);   // xaT
                u64t pv2 = bcast2(s_xpT[(d0 + dd) * 33 + lane]);
                const ulonglong2* wvr = (const ulonglong2*)(s_wbuf + h * 1024 + dd * 64 + e0);
                #pragma unroll
                for (int j = 0; j < 4; j++) {
                    ulonglong2 w2 = wvr[j];
                    aa[2 * j]     = fma2(av2, w2.x, aa[2 * j]);
                    aa[2 * j + 1] = fma2(av2, w2.y, aa[2 * j + 1]);
                    ap[2 * j]     = fma2(pv2, w2.x, ap[2 * j]);
                    ap[2 * j + 1] = fma2(pv2, w2.y, ap[2 * j + 1]);
                }
            }
            __syncthreads();
        }
        int row = h * 32 + lane;
        #pragma unroll
        for (int j = 0; j < 4; j++) {
            float2 a0 = unpk(aa[2 * j]), a1 = unpk(aa[2 * j + 1]);
            float2 p0 = unpk(ap[2 * j]), p1 = unpk(ap[2 * j + 1]);
            *(float4*)(s_ava + row * 68 + e0 + j * 4) = make_float4(a0.x, a0.y, a1.x, a1.y);
            *(float4*)(s_avp + row * 68 + e0 + j * 4) = make_float4(p0.x, p0.y, p1.x, p1.y);
        }
    }
    __syncthreads();

    // ---------------- P6a: cd = avp - ava ----------------
    #pragma unroll
    for (int g = t; g < 2048; g += 512) {
        int row = g >> 4, e0 = (g & 15) * 4;
        float4 a4 = *(const float4*)(s_ava + row * 68 + e0);
        float4 p4 = *(const float4*)(s_avp + row * 68 + e0);
        *(float4*)(s_cd + row * 68 + e0) =
            make_float4(p4.x - a4.x, p4.y - a4.y, p4.z - a4.z, p4.w - a4.w);
    }
    __syncthreads();

    // ---------------- P6b: cb = w @ ava ----------------
    {
        int h = t >> 7, u = t & 127;
        int i = u >> 2, e0 = (u & 3) * 16;
        u64t acc[8] = {0, 0, 0, 0, 0, 0, 0, 0};
        const float* wrow = s_w + h * 1024 + i * 32;
        const float* av = s_ava + (h * 32) * 68 + e0;
        #pragma unroll 4
        for (int k2 = 0; k2 < 32; k2++) {
            u64t w2 = bcast2(wrow[k2]);
            const ulonglong2* a2 = (const ulonglong2*)(av + k2 * 68);
            ulonglong2 v0 = a2[0], v1 = a2[1], v2 = a2[2], v3 = a2[3];
            acc[0] = fma2(w2, v0.x, acc[0]);
            acc[1] = fma2(w2, v0.y, acc[1]);
            acc[2] = fma2(w2, v1.x, acc[2]);
            acc[3] = fma2(w2, v1.y, acc[3]);
            acc[4] = fma2(w2, v2.x, acc[4]);
            acc[5] = fma2(w2, v2.y, acc[5]);
            acc[6] = fma2(w2, v3.x, acc[6]);
            acc[7] = fma2(w2, v3.y, acc[7]);
        }
        float* cbr = s_cb + (h * 32 + i) * 68 + e0;
        #pragma unroll
        for (int q4 = 0; q4 < 4; q4++) {
            float2 f0 = unpk(acc[q4 * 2]);
            float2 f1 = unpk(acc[q4 * 2 + 1]);
            *(float4*)(cbr + q4 * 4) = make_float4(f0.x, f0.y, f1.x, f1.y);
        }
    }
    __syncthreads();

    // ---------------- P7a: center rows, sbb/sdd ----------------
    if (t < 256) {
        float* row = ((t < 128) ? s_cb : s_cd) + (t & 127) * 68;
        float acc = 0.f;
        #pragma unroll
        for (int e0 = 0; e0 < 64; e0 += 4) {
            float4 v = *(const float4*)(row + e0);
            acc += v.x + v.y + v.z + v.w;
        }
        float mu = acc * (1.f / 64.f);
        float var = 0.f;
        #pragma unroll
        for (int e0 = 0; e0 < 64; e0 += 4) {
            float4 v = *(const float4*)(row + e0);
            v.x -= mu; v.y -= mu; v.z -= mu; v.w -= mu;
            var += v.x * v.x + v.y * v.y + v.z * v.z + v.w * v.w;
            *(float4*)(row + e0) = v;
        }
        var *= (1.f / 64.f);
        if (t < 128) s_sbb[t] = var; else s_sdd[t & 127] = var;
    }
    __syncthreads();

    // ---------------- P7b: sbd[i,j] ----------------
    {
        int h = t >> 7, u = t & 127;
        int i = u >> 2, jg = u & 3;
        u64t acc2[8] = {0, 0, 0, 0, 0, 0, 0, 0};
        const float* cbr = s_cb + (h * 32 + i) * 68;
        const float* cdr = s_cd + (h * 32 + jg * 8) * 68;
        #pragma unroll 2
        for (int e0 = 0; e0 < 64; e0 += 4) {
            ulonglong2 b2 = *(const ulonglong2*)(cbr + e0);
            #pragma unroll
            for (int jj = 0; jj < 8; jj++) {
                ulonglong2 d2 = *(const ulonglong2*)(cdr + jj * 68 + e0);
                acc2[jj] = fma2(b2.x, d2.x, acc2[jj]);
                acc2[jj] = fma2(b2.y, d2.y, acc2[jj]);
            }
        }
        #pragma unroll
        for (int jj = 0; jj < 8; jj++) {
            float2 f = unpk(acc2[jj]);
            s_sbd[h * 1024 + i * 32 + jg * 8 + jj] = (f.x + f.y) * (1.f / 64.f);
        }
    }
    __syncthreads();

    // ---------------- P7c: scale centered cb/cd by ln_g ----------------
    #pragma unroll
    for (int g = t; g < 2048; g += 512) {
        int row = g >> 4, e0 = (g & 15) * 4;
        float4 g4 = *(const float4*)(ln_g + (row >> 5) * 64 + e0);
        float4 b4 = *(const float4*)(s_cb + row * 68 + e0);
        float4 d4 = *(const float4*)(s_cd + row * 68 + e0);
        b4.x *= g4.x; b4.y *= g4.y; b4.z *= g4.z; b4.w *= g4.w;
        d4.x *= g4.x; d4.y *= g4.y; d4.z *= g4.z; d4.w *= g4.w;
        *(float4*)(s_cb + row * 68 + e0) = b4;
        *(float4*)(s_cd + row * 68 + e0) = d4;
    }
    __syncthreads();

    // ---------------- P8: A = cb@W1h, D = cd@W1h ----------------
    {
        int h = t >> 7, u = t & 127;
        int m0 = (u & 15) * 4, nr = u >> 4;
        u64t aA[4][2], aD[4][2];
        #pragma unroll
        for (int r = 0; r < 4; r++) { aA[r][0] = 0; aA[r][1] = 0; aD[r][0] = 0; aD[r][1] = 0; }
        const float* w1b = W_f1 + h * 4096 + m0;
        #pragma unroll 2
        for (int e0 = 0; e0 < 64; e0 += 4) {
            float bvv[4][4], dvv[4][4];
            #pragma unroll
            for (int r = 0; r < 4; r++) {
                int row = h * 32 + nr + 8 * r;
                float4 b4 = *(const float4*)(s_cb + row * 68 + e0);
                float4 d4 = *(const float4*)(s_cd + row * 68 + e0);
                bvv[r][0] = b4.x; bvv[r][1] = b4.y; bvv[r][2] = b4.z; bvv[r][3] = b4.w;
                dvv[r][0] = d4.x; dvv[r][1] = d4.y; dvv[r][2] = d4.z; dvv[r][3] = d4.w;
            }
            #pragma unroll
            for (int ee = 0; ee < 4; ee++) {
                ulonglong2 w2 = *(const ulonglong2*)(w1b + (e0 + ee) * 64);
                #pragma unroll
                for (int r = 0; r < 4; r++) {
                    u64t bv2 = bcast2(bvv[r][ee]);
                    u64t dv2 = bcast2(dvv[r][ee]);
                    aA[r][0] = fma2(bv2, w2.x, aA[r][0]);
                    aA[r][1] = fma2(bv2, w2.y, aA[r][1]);
                    aD[r][0] = fma2(dv2, w2.x, aD[r][0]);
                    aD[r][1] = fma2(dv2, w2.y, aD[r][1]);
                }
            }
        }
        #pragma unroll
        for (int r = 0; r < 4; r++) {
            int row = h * 32 + nr + 8 * r;
            float2 A0 = unpk(aA[r][0]), A1 = unpk(aA[r][1]);
            float2 D0 = unpk(aD[r][0]), D1 = unpk(aD[r][1]);
            *(float4*)(s_A + row * 68 + m0) = make_float4(A0.x, A0.y, A1.x, A1.y);
            *(float4*)(s_D + row * 68 + m0) = make_float4(D0.x, D0.y, D1.x, D1.y);
        }
    }
    __syncthreads();

    // ---------------- P8b: rsq in place of sbd ----------------
    #pragma unroll
    for (int g = t; g < 1024; g += 512) {
        int h = g >> 8, i = (g >> 3) & 31, j0 = (g & 7) * 4;
        int base = h * 1024 + i * 32 + j0;
        float4 w4 = *(const float4*)(s_w + base);
        float4 s4 = *(const float4*)(s_sbd + base);
        float4 dd4 = *(const float4*)(s_sdd + h * 32 + j0);
        float bb = s_sbb[h * 32 + i];
        float4 r;
        r.x = rsqrtf(bb + 2.f * w4.x * s4.x + w4.x * w4.x * dd4.x + 1e-5f);
        r.y = rsqrtf(bb + 2.f * w4.y * s4.y + w4.y * w4.y * dd4.y + 1e-5f);
        r.z = rsqrtf(bb + 2.f * w4.z * s4.z + w4.z * w4.z * dd4.z + 1e-5f);
        r.w = rsqrtf(bb + 2.f * w4.w * s4.w + w4.w * w4.w * dd4.w + 1e-5f);
        *(float4*)(s_sbd + base) = r;
    }
    __syncthreads();

    // ---------------- P9: value (sync-free loop) ----------------
    {
        int j = t >> 4, part = t & 15, m0 = part * 4;
        ulonglong2 C02 = *(const ulonglong2*)(s_C0 + m0);
        float4 W24 = *(const float4*)(s_W2 + m0);
        u64t D2[4][2];
        #pragma unroll
        for (int h = 0; h < 4; h++) {
            ulonglong2 d2 = *(const ulonglong2*)(s_D + (h * 32 + j) * 68 + m0);
            D2[h][0] = d2.x; D2[h][1] = d2.y;
        }
        #pragma unroll 1
        for (int i = 0; i < 32; i++) {
            u64t hid0 = C02.x, hid1 = C02.y;
            #pragma unroll
            for (int h = 0; h < 4; h++) {
                int idx = h * 1024 + i * 32 + j;
                u64t rq2 = bcast2(s_sbd[idx]);
                u64t wv2 = bcast2(s_w[idx]);
                ulonglong2 A2 = *(const ulonglong2*)(s_A + (h * 32 + i) * 68 + m0);
                u64t t0 = fma2(wv2, D2[h][0], A2.x);
                hid0 = fma2(rq2, t0, hid0);
                u64t t1 = fma2(wv2, D2[h][1], A2.y);
                hid1 = fma2(rq2, t1, hid1);
            }
            float2 h0 = unpk(hid0), h1 = unpk(hid1);
            float acc = LEAKY(h0.x) * W24.x + LEAKY(h0.y) * W24.y
                      + LEAKY(h1.x) * W24.z + LEAKY(h1.y) * W24.w;
            acc += __shfl_xor_sync(0xffffffffu, acc, 8);
            acc += __shfl_xor_sync(0xffffffffu, acc, 4);
            acc += __shfl_xor_sync(0xffffffffu, acc, 2);
            acc += __shfl_xor_sync(0xffffffffu, acc, 1);
            if (part == 0) out_v[b * 1024 + i * 32 + j] = acc;
        }
    }
}

extern "C" void kernel_launch(void* const* d_in, const int* in_sizes, int n_in,
                              void* d_out, int out_size) {
    const float* states   = (const float*)d_in[0];
    const float* policies = (const float*)d_in[1];
    const float* actions  = (const float*)d_in[2];
    const float* W_se     = (const float*)d_in[3];
    const float* b_se     = (const float*)d_in[4];
    const float* W_sape   = (const float*)d_in[5];
    const float* b_sape   = (const float*)d_in[6];
    const float* Wk       = (const float*)d_in[7];
    const float* Wq       = (const float*)d_in[8];
    const float* Wv       = (const float*)d_in[9];
    const float* ln_g     = (const float*)d_in[10];
    const float* ln_b     = (const float*)d_in[11];
    const float* W_f1     = (const float*)d_in[12];
    const float* W_f2     = (const float*)d_in[13];

    float* out_v = (float*)d_out;                    // [B,N,N,1]
    float* out_w = (float*)d_out + 128 * 32 * 32;    // [B,H,N,N]

    static int configured = 0;
    if (!configured) {
        cudaFuncSetAttribute(fused_gat_kernel,
                             cudaFuncAttributeMaxDynamicSharedMemorySize, SMEM_BYTES);
        configured = 1;
    }

    fused_gat_kernel<<<128, 512, SMEM_BYTES>>>(states, policies, actions,
                                               W_se, b_se, W_sape, b_sape,
                                               Wk, Wq, Wv, ln_g, ln_b,
                                               W_f1, W_f2, out_v, out_w);
}